// round 3
// baseline (speedup 1.0000x reference)
#include <cuda_runtime.h>
#include <cuda_bf16.h>
#include <mma.h>

using namespace nvcuda;

#define NROWS 8192
#define DIM   768
#define BM 64
#define BN 64
#define BK 32
#define CHUNKS 8
#define COLS_PER_CHUNK (NROWS / CHUNKS)          // 1024
#define TILES_PER_CHUNK (COLS_PER_CHUNK / BN)    // 16

// l_j = sim*20 ; exp(l-20) = exp2(sim*20*log2e - 20*log2e)
#define EXPC 28.853900817779268f
#define LN2  0.6931471805599453f

__device__ __nv_bfloat16 g_xn[(size_t)NROWS * DIM];   // normalized rows, bf16
__device__ float g_partial[CHUNKS][NROWS];            // per-chunk row sums of exp
__device__ float g_target[NROWS];                     // sim(i, i^1)

__device__ __forceinline__ float fast_exp2(float a) {
    float r;
    asm("ex2.approx.f32 %0, %1;" : "=f"(r) : "f"(a));
    return r;
}
__device__ __forceinline__ float fast_lg2(float a) {
    float r;
    asm("lg2.approx.f32 %0, %1;" : "=f"(r) : "f"(a));
    return r;
}

// ---------------------------------------------------------------------------
// Kernel 1: row-normalize x (fp32) -> g_xn (bf16)
// ---------------------------------------------------------------------------
__global__ __launch_bounds__(256) void knorm(const float* __restrict__ x) {
    int row = blockIdx.x;
    const float* xr = x + (size_t)row * DIM;
    int tid = threadIdx.x;

    float ss = 0.f;
    for (int c = tid; c < DIM; c += 256) {
        float v = xr[c];
        ss = fmaf(v, v, ss);
    }
    #pragma unroll
    for (int o = 16; o; o >>= 1) ss += __shfl_xor_sync(0xffffffffu, ss, o);

    __shared__ float sw[8];
    __shared__ float sscale;
    if ((tid & 31) == 0) sw[tid >> 5] = ss;
    __syncthreads();
    if (tid == 0) {
        float t = 0.f;
        #pragma unroll
        for (int w = 0; w < 8; w++) t += sw[w];
        sscale = 1.0f / fmaxf(sqrtf(t), 1e-8f);
    }
    __syncthreads();
    float scale = sscale;
    for (int c = tid; c < DIM; c += 256)
        g_xn[(size_t)row * DIM + c] = __float2bfloat16(xr[c] * scale);
}

// ---------------------------------------------------------------------------
// Kernel 2: tiled bf16 WMMA GEMM (sim = xn @ xn^T) with fused exp-sum epilogue.
// Block = 256 threads (8 warps, 2x4 warp grid over a 64x64 C tile).
// grid = (128 row tiles, 8 column chunks). Each block streams 16 column tiles.
// Deterministic: each (chunk,row) partial slot has exactly one writer.
// ---------------------------------------------------------------------------
__global__ __launch_bounds__(256) void kgemm() {
    __shared__ __nv_bfloat16 SA[BM][BK + 8];
    __shared__ __nv_bfloat16 SB[BN][BK + 8];
    __shared__ float         SC[BM][BN + 8];

    const int row0  = blockIdx.x * BM;
    const int chunk = blockIdx.y;
    const int tid   = threadIdx.x;
    const int warp  = tid >> 5;
    const int wm    = warp >> 2;      // 0..1  (32-row strip)
    const int wn    = warp & 3;       // 0..3  (16-col strip)
    const int r     = tid >> 2;       // epilogue row within tile (0..63)
    const int q     = tid & 3;        // epilogue col quarter (0..3)
    const int i     = row0 + r;       // global row for epilogue
    const int lr    = tid >> 2;       // smem load row (0..63)
    const int lc    = (tid & 3) * 8;  // smem load col (8 bf16 per thread)

    float partial = 0.f;

    for (int jt = 0; jt < TILES_PER_CHUNK; jt++) {
        const int j0 = chunk * COLS_PER_CHUNK + jt * BN;

        wmma::fragment<wmma::accumulator, 16, 16, 16, float> acc[2];
        #pragma unroll
        for (int m = 0; m < 2; m++) wmma::fill_fragment(acc[m], 0.0f);

        for (int kb = 0; kb < DIM; kb += BK) {
            __syncthreads();
            *(uint4*)&SA[lr][lc] = *(const uint4*)&g_xn[(size_t)(row0 + lr) * DIM + kb + lc];
            *(uint4*)&SB[lr][lc] = *(const uint4*)&g_xn[(size_t)(j0  + lr) * DIM + kb + lc];
            __syncthreads();

            #pragma unroll
            for (int kf = 0; kf < 2; kf++) {
                wmma::fragment<wmma::matrix_b, 16, 16, 16, __nv_bfloat16, wmma::col_major> bf;
                wmma::load_matrix_sync(bf, &SB[wn * 16][kf * 16], BK + 8);
                #pragma unroll
                for (int m = 0; m < 2; m++) {
                    wmma::fragment<wmma::matrix_a, 16, 16, 16, __nv_bfloat16, wmma::row_major> af;
                    wmma::load_matrix_sync(af, &SA[wm * 32 + m * 16][kf * 16], BK + 8);
                    wmma::mma_sync(acc[m], af, bf, acc[m]);
                }
            }
        }

        // Dump C tile to shared, then fused epilogue.
        #pragma unroll
        for (int m = 0; m < 2; m++)
            wmma::store_matrix_sync(&SC[wm * 32 + m * 16][wn * 16], acc[m], BN + 8,
                                    wmma::mem_row_major);
        __syncthreads();

        const float* crow = &SC[r][q * 16];
        #pragma unroll
        for (int c = 0; c < 16; c++) {
            int j = j0 + q * 16 + c;
            float v = crow[c];
            if (j == (i ^ 1)) g_target[i] = v;       // unique global writer
            if (j != i)
                partial += fast_exp2(fmaf(v, EXPC, -EXPC));
        }
        // Next iteration's SA/SB writes are fenced by the syncthreads inside the
        // k-loop; SC rewrite happens only after that loop's barriers.
    }

    // Reduce the 4 column-quarter partials of each row (lanes r*4+q are
    // consecutive within a warp).
    partial += __shfl_xor_sync(0xffffffffu, partial, 1);
    partial += __shfl_xor_sync(0xffffffffu, partial, 2);
    if (q == 0) g_partial[chunk][i] = partial;
}

// ---------------------------------------------------------------------------
// Kernel 3: loss_i = 20 + ln(S_i) - 20*sim_target_i ; out = mean(loss)
// ---------------------------------------------------------------------------
__global__ __launch_bounds__(1024) void kreduce(float* __restrict__ out) {
    int tid = threadIdx.x;
    float s = 0.f;
    for (int i = tid; i < NROWS; i += 1024) {
        float S = 0.f;
        #pragma unroll
        for (int c = 0; c < CHUNKS; c++) S += g_partial[c][i];
        s += 20.0f + LN2 * fast_lg2(S) - 20.0f * g_target[i];
    }
    #pragma unroll
    for (int o = 16; o; o >>= 1) s += __shfl_xor_sync(0xffffffffu, s, o);

    __shared__ float sw[32];
    if ((tid & 31) == 0) sw[tid >> 5] = s;
    __syncthreads();
    if (tid < 32) {
        s = sw[tid];
        #pragma unroll
        for (int o = 16; o; o >>= 1) s += __shfl_xor_sync(0xffffffffu, s, o);
        if (tid == 0) out[0] = s * (1.0f / NROWS);
    }
}

// ---------------------------------------------------------------------------
extern "C" void kernel_launch(void* const* d_in, const int* in_sizes, int n_in,
                              void* d_out, int out_size) {
    const float* x = (const float*)d_in[0];
    float* out = (float*)d_out;

    knorm<<<NROWS, 256>>>(x);
    kgemm<<<dim3(NROWS / BM, CHUNKS), 256>>>();
    kreduce<<<1, 1024>>>(out);
}

// round 5
// speedup vs baseline: 2.6085x; 2.6085x over previous
#include <cuda_runtime.h>
#include <cuda_bf16.h>
#include <mma.h>
#include <cstdint>

#define NROWS 8192
#define DIM   768
#define CHUNKS 2                    // grid.y column halves
#define COLS_PER_CTA (NROWS / CHUNKS)   // 4096
#define NT (COLS_PER_CTA / 128)         // 32 column tiles of N=128
#define KCH (DIM / 64)                  // 12 K-chunks of 64

#define EXPC 28.853900817779268f
#define LN2  0.6931471805599453f

// smem map (dynamic):
//   [0]        u32 tmem base
//   [16..80)   mbarriers: bfull[2]@16, bfree[2]@32, mdone[2]@48, dfree[2]@64
//   [1024)     A: 12 chunks x (128 rows x 128B, SW128)          = 196608
//   [197632)   B: 2 stages x (128 rows x 128B, SW128)           = 32768
#define A_OFF 1024
#define B_OFF (1024 + 196608)
#define SMEM_TOTAL (1024 + 196608 + 32768)   // 230400 <= 232448

// idesc kind::f16: F32 accum, BF16 a/b, N=128, M=128
#define IDESC ((1u<<4)|(1u<<7)|(1u<<10)|((128u/8u)<<17)|((128u/16u)<<24))

#define SWZ(o) ((o) ^ (((o) >> 3) & 0x70))

__device__ __align__(256) __nv_bfloat16 g_xn[(size_t)NROWS * DIM];
__device__ float g_partial[CHUNKS][NROWS];
__device__ float g_target[NROWS];

// ---------------------------------------------------------------------------
// PTX helpers
// ---------------------------------------------------------------------------
__device__ __forceinline__ uint32_t smem_u32(const void* p) {
    uint32_t a;
    asm("{ .reg .u64 t; cvta.to.shared.u64 t, %1; cvt.u32.u64 %0, t; }"
        : "=r"(a) : "l"(p));
    return a;
}
__device__ __forceinline__ float fast_exp2(float a) {
    float r; asm("ex2.approx.f32 %0, %1;" : "=f"(r) : "f"(a)); return r;
}
__device__ __forceinline__ float fast_lg2(float a) {
    float r; asm("lg2.approx.f32 %0, %1;" : "=f"(r) : "f"(a)); return r;
}
__device__ __forceinline__ void cp16(uint32_t dst, const void* src) {
    asm volatile("cp.async.cg.shared.global [%0], [%1], 16;" :: "r"(dst), "l"(src));
}
#define CP_COMMIT() asm volatile("cp.async.commit_group;" ::: "memory")
#define CP_WAIT0()  asm volatile("cp.async.wait_group 0;" ::: "memory")
#define CP_WAIT1()  asm volatile("cp.async.wait_group 1;" ::: "memory")
#define FENCE_ASYNC_SHARED() asm volatile("fence.proxy.async.shared::cta;" ::: "memory")

#define MBARRIER_INIT(a, n) \
    asm volatile("mbarrier.init.shared.b64 [%0], %1;" :: "r"((uint32_t)(a)), "r"((uint32_t)(n)) : "memory")
#define MBARRIER_ARRIVE(a) \
    asm volatile("mbarrier.arrive.shared.b64 _, [%0];" :: "r"((uint32_t)(a)) : "memory")
#define MBARRIER_WAIT_PARITY(a, par) do { \
    uint32_t _m = (uint32_t)(a); uint32_t _p = (uint32_t)(par); uint32_t _d; \
    asm volatile("{\n\t.reg .pred p;\n\t" \
        "mbarrier.try_wait.parity.acquire.cta.shared::cta.b64 p, [%1], %2;\n\t" \
        "selp.b32 %0, 1, 0, p;\n\t}" : "=r"(_d) : "r"(_m), "r"(_p) : "memory"); \
    if (!_d) { \
        asm volatile("{\n\t.reg .pred P1;\n\t" \
            "WL_%=:\n\t" \
            "mbarrier.try_wait.parity.acquire.cta.shared::cta.b64 P1, [%0], %1, 0x989680;\n\t" \
            "@P1 bra.uni WD_%=;\n\t" \
            "bra.uni WL_%=;\n\t" \
            "WD_%=:\n\t}" :: "r"(_m), "r"(_p) : "memory"); \
    } } while (0)

#define TCGEN05_ALLOC(sa, n) \
    asm volatile("tcgen05.alloc.cta_group::1.sync.aligned.shared::cta.b32 [%0], %1;" \
        :: "r"((uint32_t)(sa)), "r"((uint32_t)(n)) : "memory")
#define TCGEN05_DEALLOC(t, n) \
    asm volatile("tcgen05.dealloc.cta_group::1.sync.aligned.b32 %0, %1;" :: "r"(t), "r"((uint32_t)(n)))
#define TCGEN05_RELINQ() \
    asm volatile("tcgen05.relinquish_alloc_permit.cta_group::1.sync.aligned;")
#define TCGEN05_COMMIT(a) \
    asm volatile("tcgen05.commit.cta_group::1.mbarrier::arrive::one.shared::cluster.b64 [%0];" \
        :: "r"((uint32_t)(a)) : "memory")
#define TCGEN05_FENCE_BEFORE() asm volatile("tcgen05.fence::before_thread_sync;" ::: "memory")
#define TCGEN05_FENCE_AFTER()  asm volatile("tcgen05.fence::after_thread_sync;" ::: "memory")
#define TCGEN05_WAIT_LD()      asm volatile("tcgen05.wait::ld.sync.aligned;" ::: "memory")

#define TCGEN05_LD_32X32B_X32(r, tmem_addr) \
    asm volatile( \
        "tcgen05.ld.sync.aligned.32x32b.x32.b32 " \
        "{%0, %1, %2, %3, %4, %5, %6, %7, " \
        " %8, %9, %10, %11, %12, %13, %14, %15, " \
        " %16, %17, %18, %19, %20, %21, %22, %23, " \
        " %24, %25, %26, %27, %28, %29, %30, %31}, [%32];" \
        : "=r"((r)[0]),  "=r"((r)[1]),  "=r"((r)[2]),  "=r"((r)[3]), \
          "=r"((r)[4]),  "=r"((r)[5]),  "=r"((r)[6]),  "=r"((r)[7]), \
          "=r"((r)[8]),  "=r"((r)[9]),  "=r"((r)[10]), "=r"((r)[11]), \
          "=r"((r)[12]), "=r"((r)[13]), "=r"((r)[14]), "=r"((r)[15]), \
          "=r"((r)[16]), "=r"((r)[17]), "=r"((r)[18]), "=r"((r)[19]), \
          "=r"((r)[20]), "=r"((r)[21]), "=r"((r)[22]), "=r"((r)[23]), \
          "=r"((r)[24]), "=r"((r)[25]), "=r"((r)[26]), "=r"((r)[27]), \
          "=r"((r)[28]), "=r"((r)[29]), "=r"((r)[30]), "=r"((r)[31]) \
        : "r"(tmem_addr))

// SW128 SMEM descriptor (layout=2, version=1, LBO=1, SBO=64); +2 per K=16 bf16.
__device__ __forceinline__ uint64_t make_desc(uint32_t addr) {
    return ((uint64_t)2 << 61) | ((uint64_t)1 << 46) | ((uint64_t)64 << 32) |
           ((uint64_t)1 << 16) | (uint64_t)((addr >> 4) & 0x3FFF);
}

#if defined(__CUDA_ARCH__) && defined(__CUDA_ARCH_FEAT_SM103_ALL)
#define HAS_TCGEN05 1
__device__ __forceinline__ void mma_f16_ss(uint32_t d, uint64_t ad, uint64_t bd,
                                           uint32_t idesc, uint32_t en) {
    asm volatile(
        "{\n\t"
        ".reg .pred p;\n\t"
        "setp.ne.u32 p, %4, 0;\n\t"
        "tcgen05.mma.cta_group::1.kind::f16 [%0], %1, %2, %3, {%5, %5, %5, %5}, p;\n\t"
        "}"
        :: "r"(d), "l"(ad), "l"(bd), "r"(idesc), "r"(en), "r"(0u)
        : "memory");
}
#endif

// ---------------------------------------------------------------------------
// Kernel 1: warp-per-row normalize fp32 -> bf16 (no smem, no block reduce)
// ---------------------------------------------------------------------------
__global__ __launch_bounds__(256) void knorm(const float* __restrict__ x) {
    int row = (blockIdx.x << 3) + (threadIdx.x >> 5);
    int l   = threadIdx.x & 31;
    const float4* xr = (const float4*)(x + (size_t)row * DIM) + l * 6;

    float4 v[6];
    float ss = 0.f;
    #pragma unroll
    for (int u = 0; u < 6; u++) {
        v[u] = xr[u];
        ss = fmaf(v[u].x, v[u].x, ss);
        ss = fmaf(v[u].y, v[u].y, ss);
        ss = fmaf(v[u].z, v[u].z, ss);
        ss = fmaf(v[u].w, v[u].w, ss);
    }
    #pragma unroll
    for (int o = 16; o; o >>= 1) ss += __shfl_xor_sync(0xffffffffu, ss, o);
    float scale = 1.0f / fmaxf(sqrtf(ss), 1e-8f);

    uint32_t o[12];
    #pragma unroll
    for (int u = 0; u < 6; u++) {
        __nv_bfloat162 p0 = __floats2bfloat162_rn(v[u].x * scale, v[u].y * scale);
        __nv_bfloat162 p1 = __floats2bfloat162_rn(v[u].z * scale, v[u].w * scale);
        o[2 * u]     = *(uint32_t*)&p0;
        o[2 * u + 1] = *(uint32_t*)&p1;
    }
    uint4* dst = (uint4*)(g_xn + (size_t)row * DIM) + l * 3;
    dst[0] = make_uint4(o[0], o[1], o[2],  o[3]);
    dst[1] = make_uint4(o[4], o[5], o[6],  o[7]);
    dst[2] = make_uint4(o[8], o[9], o[10], o[11]);
}

// ---------------------------------------------------------------------------
// Kernel 2: sim = xn @ xn^T with fused exp-sum epilogue.
// sm_103a pass: tcgen05 warp-specialized (warps 0-3 epilogue, warp 4 lane 0
// MMA issuer, warps 5-6 B producers). A (128x768) persistent in SMEM.
// non-103a PTX pass: WMMA fallback (same launch config) so every compile
// pass is valid; runtime selects the exact-arch sm_103a SASS.
// ---------------------------------------------------------------------------
__global__ __launch_bounds__(256, 1) __cluster_dims__(1, 1, 1) void kgemm() {
    extern __shared__ char smem[];
    const int tid = threadIdx.x;
    const int i0    = blockIdx.x * 128;
    const int jbase = blockIdx.y * COLS_PER_CTA;

#if defined(HAS_TCGEN05)
    const uint32_t sb  = smem_u32(smem);
    const int wid = tid >> 5;

    const uint32_t MB_BFULL = sb + 16;
    const uint32_t MB_BFREE = sb + 32;
    const uint32_t MB_MDONE = sb + 48;
    const uint32_t MB_DFREE = sb + 64;

    if (tid == 0) {
        MBARRIER_INIT(MB_BFULL + 0, 64); MBARRIER_INIT(MB_BFULL + 8, 64);
        MBARRIER_INIT(MB_BFREE + 0, 1);  MBARRIER_INIT(MB_BFREE + 8, 1);
        MBARRIER_INIT(MB_MDONE + 0, 1);  MBARRIER_INIT(MB_MDONE + 8, 1);
        MBARRIER_INIT(MB_DFREE + 0, 128); MBARRIER_INIT(MB_DFREE + 8, 128);
    }
    if (wid == 4) TCGEN05_ALLOC(sb, 512);
    __syncthreads();
    uint32_t tmem;
    asm volatile("ld.shared.b32 %0, [%1];" : "=r"(tmem) : "r"(sb));

    // ---- prologue: load persistent A (12 chunks x 128 rows x 128B, SW128) ----
    #pragma unroll 1
    for (int q = 0; q < 48; q++) {
        int idx = tid + 256 * q;               // 0..12287
        int c = idx >> 10, rem = idx & 1023, r = rem >> 3, u = rem & 7;
        uint32_t off = (uint32_t)(r * 128 + u * 16);
        cp16(sb + A_OFF + c * 16384 + SWZ(off),
             &g_xn[(size_t)(i0 + r) * DIM + c * 64 + u * 8]);
    }
    CP_COMMIT(); CP_WAIT0();
    FENCE_ASYNC_SHARED();
    __syncthreads();

    if (wid < 4) {
        // ================= consumers: epilogue on D buffers =================
        const int l = tid & 31;
        const int i = i0 + wid * 32 + l;
        float partial = 0.f;
        #pragma unroll 1
        for (int t = 0; t < NT; t++) {
            const int b = t & 1;
            MBARRIER_WAIT_PARITY(MB_MDONE + b * 8, (t >> 1) & 1);
            TCGEN05_FENCE_AFTER();
            const int j0 = jbase + t * 128;
            #pragma unroll 1
            for (int g = 0; g < 4; g++) {
                uint32_t rr[32];
                TCGEN05_LD_32X32B_X32(rr, tmem + b * 128 + g * 32);
                TCGEN05_WAIT_LD();
                const int jg = j0 + g * 32;
                unsigned di = (unsigned)(i - jg);
                unsigned dt = (unsigned)((i ^ 1) - jg);
                if (di < 32u || dt < 32u) {
                    #pragma unroll
                    for (int c = 0; c < 32; c++) {
                        float v = __uint_as_float(rr[c]);
                        int j = jg + c;
                        if (j == (i ^ 1)) g_target[i] = v;
                        if (j != i)
                            partial += fast_exp2(fmaf(v, EXPC, -EXPC));
                    }
                } else {
                    #pragma unroll
                    for (int c = 0; c < 32; c++)
                        partial += fast_exp2(fmaf(__uint_as_float(rr[c]), EXPC, -EXPC));
                }
            }
            TCGEN05_FENCE_BEFORE();
            MBARRIER_ARRIVE(MB_DFREE + b * 8);
        }
        g_partial[blockIdx.y][i] = partial;
    } else if (tid == 128) {
        // ================= MMA issuer =================
        #pragma unroll 1
        for (int t = 0; t < NT; t++) {
            const int b = t & 1;
            if (t >= 2) {
                MBARRIER_WAIT_PARITY(MB_DFREE + b * 8, ((t >> 1) + 1) & 1);
                TCGEN05_FENCE_AFTER();
            }
            #pragma unroll 1
            for (int c = 0; c < KCH; c++) {
                const int n = t * KCH + c, s = n & 1;
                MBARRIER_WAIT_PARITY(MB_BFULL + s * 8, (n >> 1) & 1);
                uint64_t ad = make_desc(sb + A_OFF + c * 16384);
                uint64_t bd = make_desc(sb + B_OFF + s * 16384);
                #pragma unroll
                for (int k4 = 0; k4 < 4; k4++)
                    mma_f16_ss(tmem + b * 128, ad + k4 * 2, bd + k4 * 2, IDESC,
                               (uint32_t)((c | k4) != 0));
                TCGEN05_COMMIT(MB_BFREE + s * 8);
            }
            TCGEN05_COMMIT(MB_MDONE + b * 8);
        }
    } else if (wid == 5 || wid == 6) {
        // ================= B producers (64 threads) =================
        const int ptid = tid - 160;           // 0..63
        const int r0 = ptid * 2;
        #pragma unroll 1
        for (int n = 0; n < NT * KCH; n++) {
            const int s = n & 1, m = n >> 1;
            if (m >= 1) MBARRIER_WAIT_PARITY(MB_BFREE + s * 8, (m - 1) & 1);
            const int t = n / KCH, c = n % KCH;
            const int j0 = jbase + t * 128, kb = c * 64;
            const uint32_t bbase = sb + B_OFF + s * 16384;
            #pragma unroll
            for (int rr = 0; rr < 2; rr++) {
                const int row = r0 + rr;
                const __nv_bfloat16* src = &g_xn[(size_t)(j0 + row) * DIM + kb];
                #pragma unroll
                for (int u = 0; u < 8; u++)
                    cp16(bbase + SWZ((uint32_t)(row * 128 + u * 16)), src + u * 8);
            }
            CP_COMMIT();
            if (n > 0) {          // deferred arrive for previous fill
                CP_WAIT1();
                FENCE_ASYNC_SHARED();
                MBARRIER_ARRIVE(MB_BFULL + ((n - 1) & 1) * 8);
            }
        }
        CP_WAIT0();
        FENCE_ASYNC_SHARED();
        MBARRIER_ARRIVE(MB_BFULL + ((NT * KCH - 1) & 1) * 8);
    }
    // warp 7 and warp-4 lanes 1..31 fall through

    __syncthreads();
    if (wid == 4) {
        TCGEN05_RELINQ();
        TCGEN05_DEALLOC(tmem, 512);
    }
#else
    // =================== WMMA fallback (non-103a compile passes) ============
    using namespace nvcuda;
    __nv_bfloat16* SA = (__nv_bfloat16*)(smem);           // [64][40]
    __nv_bfloat16* SB = (__nv_bfloat16*)(smem + 8192);    // [64][40]
    float*         SC = (float*)(smem + 16384);           // [64][72]
    const int warp = tid >> 5;
    const int wm = warp >> 2, wn = warp & 3;
    const int r = tid >> 2, q = tid & 3;
    const int lr = tid >> 2, lc = (tid & 3) * 8;

    for (int ms = 0; ms < 2; ms++) {
        const int row0 = i0 + ms * 64;
        const int i = row0 + r;
        float partial = 0.f;
        for (int jt = 0; jt < COLS_PER_CTA / 64; jt++) {
            const int j0 = jbase + jt * 64;
            wmma::fragment<wmma::accumulator, 16, 16, 16, float> acc[2];
            #pragma unroll
            for (int m = 0; m < 2; m++) wmma::fill_fragment(acc[m], 0.0f);

            for (int kb = 0; kb < DIM; kb += 32) {
                __syncthreads();
                *(uint4*)&SA[lr * 40 + lc] = *(const uint4*)&g_xn[(size_t)(row0 + lr) * DIM + kb + lc];
                *(uint4*)&SB[lr * 40 + lc] = *(const uint4*)&g_xn[(size_t)(j0  + lr) * DIM + kb + lc];
                __syncthreads();
                #pragma unroll
                for (int kf = 0; kf < 2; kf++) {
                    wmma::fragment<wmma::matrix_b, 16, 16, 16, __nv_bfloat16, wmma::col_major> bf;
                    wmma::load_matrix_sync(bf, &SB[(wn * 16) * 40 + kf * 16], 40);
                    #pragma unroll
                    for (int m = 0; m < 2; m++) {
                        wmma::fragment<wmma::matrix_a, 16, 16, 16, __nv_bfloat16, wmma::row_major> af;
                        wmma::load_matrix_sync(af, &SA[(wm * 32 + m * 16) * 40 + kf * 16], 40);
                        wmma::mma_sync(acc[m], af, bf, acc[m]);
                    }
                }
            }
            #pragma unroll
            for (int m = 0; m < 2; m++)
                wmma::store_matrix_sync(&SC[(wm * 32 + m * 16) * 72 + wn * 16], acc[m], 72,
                                        wmma::mem_row_major);
            __syncthreads();

            const float* crow = &SC[r * 72 + q * 16];
            #pragma unroll
            for (int c = 0; c < 16; c++) {
                int j = j0 + q * 16 + c;
                float v = crow[c];
                if (j == (i ^ 1)) g_target[i] = v;
                if (j != i)
                    partial += fast_exp2(fmaf(v, EXPC, -EXPC));
            }
        }
        partial += __shfl_xor_sync(0xffffffffu, partial, 1);
        partial += __shfl_xor_sync(0xffffffffu, partial, 2);
        if (q == 0) g_partial[blockIdx.y][i] = partial;
        __syncthreads();
    }
#endif
}

// ---------------------------------------------------------------------------
// Kernel 3: loss_i = 20 + ln(S_i) - 20*sim_target_i ; out = mean(loss)
// ---------------------------------------------------------------------------
__global__ __launch_bounds__(1024) void kreduce(float* __restrict__ out) {
    int tid = threadIdx.x;
    float s = 0.f;
    for (int i = tid; i < NROWS; i += 1024) {
        float S = g_partial[0][i] + g_partial[1][i];
        s += 20.0f + LN2 * fast_lg2(S) - 20.0f * g_target[i];
    }
    #pragma unroll
    for (int o = 16; o; o >>= 1) s += __shfl_xor_sync(0xffffffffu, s, o);

    __shared__ float sw[32];
    if ((tid & 31) == 0) sw[tid >> 5] = s;
    __syncthreads();
    if (tid < 32) {
        s = sw[tid];
        #pragma unroll
        for (int o = 16; o; o >>= 1) s += __shfl_xor_sync(0xffffffffu, s, o);
        if (tid == 0) out[0] = s * (1.0f / NROWS);
    }
}

// ---------------------------------------------------------------------------
extern "C" void kernel_launch(void* const* d_in, const int* in_sizes, int n_in,
                              void* d_out, int out_size) {
    const float* x = (const float*)d_in[0];
    float* out = (float*)d_out;

    cudaFuncSetAttribute(kgemm, cudaFuncAttributeMaxDynamicSharedMemorySize, SMEM_TOTAL);

    knorm<<<NROWS / 8, 256>>>(x);
    kgemm<<<dim3(NROWS / 128, CHUNKS), 256, SMEM_TOTAL>>>();
    kreduce<<<1, 1024>>>(out);
}

// round 7
// speedup vs baseline: 3.1893x; 1.2226x over previous
#include <cuda_runtime.h>
#include <cuda_bf16.h>
#include <mma.h>
#include <cstdint>

#define NROWS 8192
#define DIM   768
#define CHUNKS 2                        // grid.y column halves
#define COLS_PER_CTA (NROWS / CHUNKS)   // 4096
#define NTILE (COLS_PER_CTA / 64)       // 64 column tiles of N=64
#define KCPT 6                          // K=128 chunks per tile (768/128)
#define NCHUNK (NTILE * KCPT)           // 384 pipeline chunks per CTA
#define NSTAGE 8                        // B pipeline depth
#define STAGE_BYTES 16384               // 64 rows x 2 x 128B sub-blocks

#define EXPC 28.853900817779268f
#define LN2  0.6931471805599453f

// smem: [0] tmem ptr | [16..80) BFULL[8] | [80..144) BFREE[8]
//       [144..160) MDONE[2] | [160..176) DFREE[2] | [1024) B stages
#define B_OFF 1024
#define SMEM_TOTAL (1024 + NSTAGE * STAGE_BYTES)   // 132096

// TMEM: A cols 0..383 (K=768 bf16, 8 cols per K=16), D at 384 + b*64
#define TMEM_D 384

// idesc kind::f16: F32 accum, BF16 a/b, N=64, M=128
#define IDESC ((1u<<4)|(1u<<7)|(1u<<10)|((64u/8u)<<17)|((128u/16u)<<24))

#define SWZ(o) ((o) ^ (((o) >> 3) & 0x70))

__device__ __align__(256) __nv_bfloat16 g_xn[(size_t)NROWS * DIM];
__device__ float g_partial[CHUNKS][NROWS];
__device__ float g_target[NROWS];

// ---------------------------------------------------------------------------
// PTX helpers
// ---------------------------------------------------------------------------
__device__ __forceinline__ uint32_t smem_u32(const void* p) {
    uint32_t a;
    asm("{ .reg .u64 t; cvta.to.shared.u64 t, %1; cvt.u32.u64 %0, t; }"
        : "=r"(a) : "l"(p));
    return a;
}
__device__ __forceinline__ float fast_exp2(float a) {
    float r; asm("ex2.approx.f32 %0, %1;" : "=f"(r) : "f"(a)); return r;
}
__device__ __forceinline__ float fast_lg2(float a) {
    float r; asm("lg2.approx.f32 %0, %1;" : "=f"(r) : "f"(a)); return r;
}
__device__ __forceinline__ void cp16(uint32_t dst, const void* src) {
    asm volatile("cp.async.cg.shared.global [%0], [%1], 16;" :: "r"(dst), "l"(src));
}
#define CP_COMMIT() asm volatile("cp.async.commit_group;" ::: "memory")
#define CP_WAIT0()  asm volatile("cp.async.wait_group 0;" ::: "memory")
#define CP_WAIT1()  asm volatile("cp.async.wait_group 1;" ::: "memory")
#define CP_WAIT2()  asm volatile("cp.async.wait_group 2;" ::: "memory")
#define FENCE_ASYNC_SHARED() asm volatile("fence.proxy.async.shared::cta;" ::: "memory")

#define MBARRIER_INIT(a, n) \
    asm volatile("mbarrier.init.shared.b64 [%0], %1;" :: "r"((uint32_t)(a)), "r"((uint32_t)(n)) : "memory")
#define MBARRIER_ARRIVE(a) \
    asm volatile("mbarrier.arrive.shared.b64 _, [%0];" :: "r"((uint32_t)(a)) : "memory")
#define MBARRIER_WAIT_PARITY(a, par) do { \
    uint32_t _m = (uint32_t)(a); uint32_t _p = (uint32_t)(par); uint32_t _d; \
    asm volatile("{\n\t.reg .pred p;\n\t" \
        "mbarrier.try_wait.parity.acquire.cta.shared::cta.b64 p, [%1], %2;\n\t" \
        "selp.b32 %0, 1, 0, p;\n\t}" : "=r"(_d) : "r"(_m), "r"(_p) : "memory"); \
    if (!_d) { \
        asm volatile("{\n\t.reg .pred P1;\n\t" \
            "WL_%=:\n\t" \
            "mbarrier.try_wait.parity.acquire.cta.shared::cta.b64 P1, [%0], %1, 0x989680;\n\t" \
            "@P1 bra.uni WD_%=;\n\t" \
            "bra.uni WL_%=;\n\t" \
            "WD_%=:\n\t}" :: "r"(_m), "r"(_p) : "memory"); \
    } } while (0)

#define TCGEN05_ALLOC(sa, n) \
    asm volatile("tcgen05.alloc.cta_group::1.sync.aligned.shared::cta.b32 [%0], %1;" \
        :: "r"((uint32_t)(sa)), "r"((uint32_t)(n)) : "memory")
#define TCGEN05_DEALLOC(t, n) \
    asm volatile("tcgen05.dealloc.cta_group::1.sync.aligned.b32 %0, %1;" :: "r"(t), "r"((uint32_t)(n)))
#define TCGEN05_RELINQ() \
    asm volatile("tcgen05.relinquish_alloc_permit.cta_group::1.sync.aligned;")
#define TCGEN05_COMMIT(a) \
    asm volatile("tcgen05.commit.cta_group::1.mbarrier::arrive::one.shared::cluster.b64 [%0];" \
        :: "r"((uint32_t)(a)) : "memory")
#define TCGEN05_FENCE_BEFORE() asm volatile("tcgen05.fence::before_thread_sync;" ::: "memory")
#define TCGEN05_FENCE_AFTER()  asm volatile("tcgen05.fence::after_thread_sync;" ::: "memory")
#define TCGEN05_WAIT_LD()      asm volatile("tcgen05.wait::ld.sync.aligned;" ::: "memory")
#define TCGEN05_WAIT_ST()      asm volatile("tcgen05.wait::st.sync.aligned;" ::: "memory")

#define TCGEN05_LD_32X32B_X32(r, tmem_addr) \
    asm volatile( \
        "tcgen05.ld.sync.aligned.32x32b.x32.b32 " \
        "{%0, %1, %2, %3, %4, %5, %6, %7, " \
        " %8, %9, %10, %11, %12, %13, %14, %15, " \
        " %16, %17, %18, %19, %20, %21, %22, %23, " \
        " %24, %25, %26, %27, %28, %29, %30, %31}, [%32];" \
        : "=r"((r)[0]),  "=r"((r)[1]),  "=r"((r)[2]),  "=r"((r)[3]), \
          "=r"((r)[4]),  "=r"((r)[5]),  "=r"((r)[6]),  "=r"((r)[7]), \
          "=r"((r)[8]),  "=r"((r)[9]),  "=r"((r)[10]), "=r"((r)[11]), \
          "=r"((r)[12]), "=r"((r)[13]), "=r"((r)[14]), "=r"((r)[15]), \
          "=r"((r)[16]), "=r"((r)[17]), "=r"((r)[18]), "=r"((r)[19]), \
          "=r"((r)[20]), "=r"((r)[21]), "=r"((r)[22]), "=r"((r)[23]), \
          "=r"((r)[24]), "=r"((r)[25]), "=r"((r)[26]), "=r"((r)[27]), \
          "=r"((r)[28]), "=r"((r)[29]), "=r"((r)[30]), "=r"((r)[31]) \
        : "r"(tmem_addr))

#define TCGEN05_ST_32X32B_X64(tmem_addr, r) \
    asm volatile( \
        "tcgen05.st.sync.aligned.32x32b.x64.b32 [%0], " \
        "{%1, %2, %3, %4, %5, %6, %7, %8, " \
        " %9, %10, %11, %12, %13, %14, %15, %16, " \
        " %17, %18, %19, %20, %21, %22, %23, %24, " \
        " %25, %26, %27, %28, %29, %30, %31, %32, " \
        " %33, %34, %35, %36, %37, %38, %39, %40, " \
        " %41, %42, %43, %44, %45, %46, %47, %48, " \
        " %49, %50, %51, %52, %53, %54, %55, %56, " \
        " %57, %58, %59, %60, %61, %62, %63, %64};" \
        :: "r"(tmem_addr), \
           "r"((r)[0]),  "r"((r)[1]),  "r"((r)[2]),  "r"((r)[3]), \
           "r"((r)[4]),  "r"((r)[5]),  "r"((r)[6]),  "r"((r)[7]), \
           "r"((r)[8]),  "r"((r)[9]),  "r"((r)[10]), "r"((r)[11]), \
           "r"((r)[12]), "r"((r)[13]), "r"((r)[14]), "r"((r)[15]), \
           "r"((r)[16]), "r"((r)[17]), "r"((r)[18]), "r"((r)[19]), \
           "r"((r)[20]), "r"((r)[21]), "r"((r)[22]), "r"((r)[23]), \
           "r"((r)[24]), "r"((r)[25]), "r"((r)[26]), "r"((r)[27]), \
           "r"((r)[28]), "r"((r)[29]), "r"((r)[30]), "r"((r)[31]), \
           "r"((r)[32]), "r"((r)[33]), "r"((r)[34]), "r"((r)[35]), \
           "r"((r)[36]), "r"((r)[37]), "r"((r)[38]), "r"((r)[39]), \
           "r"((r)[40]), "r"((r)[41]), "r"((r)[42]), "r"((r)[43]), \
           "r"((r)[44]), "r"((r)[45]), "r"((r)[46]), "r"((r)[47]), \
           "r"((r)[48]), "r"((r)[49]), "r"((r)[50]), "r"((r)[51]), \
           "r"((r)[52]), "r"((r)[53]), "r"((r)[54]), "r"((r)[55]), \
           "r"((r)[56]), "r"((r)[57]), "r"((r)[58]), "r"((r)[59]), \
           "r"((r)[60]), "r"((r)[61]), "r"((r)[62]), "r"((r)[63]) \
        : "memory")

// SW128 SMEM descriptor (layout=2, version=1, LBO=1, SBO=64); +2 per K=16 bf16.
__device__ __forceinline__ uint64_t make_desc(uint32_t addr) {
    return ((uint64_t)2 << 61) | ((uint64_t)1 << 46) | ((uint64_t)64 << 32) |
           ((uint64_t)1 << 16) | (uint64_t)((addr >> 4) & 0x3FFF);
}

#if defined(__CUDA_ARCH__) && defined(__CUDA_ARCH_FEAT_SM103_ALL)
#define HAS_TCGEN05 1
// TS form: A in TMEM, B via SMEM descriptor (validated pattern: test_mma_iter)
__device__ __forceinline__ void mma_f16_ts(uint32_t d, uint32_t a_tmem, uint64_t bd,
                                           uint32_t idesc, uint32_t en) {
    asm volatile(
        "{\n\t"
        ".reg .pred p;\n\t"
        "setp.ne.u32 p, %4, 0;\n\t"
        "tcgen05.mma.cta_group::1.kind::f16 [%0], [%1], %2, %3, {%5, %5, %5, %5}, p;\n\t"
        "}"
        :: "r"(d), "r"(a_tmem), "l"(bd), "r"(idesc), "r"(en), "r"(0u)
        : "memory");
}
#endif

// ---------------------------------------------------------------------------
// Kernel 1: warp-per-row normalize fp32 -> bf16
// ---------------------------------------------------------------------------
__global__ __launch_bounds__(256) void knorm(const float* __restrict__ x) {
    int row = (blockIdx.x << 3) + (threadIdx.x >> 5);
    int l   = threadIdx.x & 31;
    const float4* xr = (const float4*)(x + (size_t)row * DIM) + l * 6;

    float4 v[6];
    float ss = 0.f;
    #pragma unroll
    for (int u = 0; u < 6; u++) {
        v[u] = xr[u];
        ss = fmaf(v[u].x, v[u].x, ss);
        ss = fmaf(v[u].y, v[u].y, ss);
        ss = fmaf(v[u].z, v[u].z, ss);
        ss = fmaf(v[u].w, v[u].w, ss);
    }
    #pragma unroll
    for (int o = 16; o; o >>= 1) ss += __shfl_xor_sync(0xffffffffu, ss, o);
    float scale = 1.0f / fmaxf(sqrtf(ss), 1e-8f);

    uint32_t o[12];
    #pragma unroll
    for (int u = 0; u < 6; u++) {
        __nv_bfloat162 p0 = __floats2bfloat162_rn(v[u].x * scale, v[u].y * scale);
        __nv_bfloat162 p1 = __floats2bfloat162_rn(v[u].z * scale, v[u].w * scale);
        o[2 * u]     = *(uint32_t*)&p0;
        o[2 * u + 1] = *(uint32_t*)&p1;
    }
    uint4* dst = (uint4*)(g_xn + (size_t)row * DIM) + l * 3;
    dst[0] = make_uint4(o[0], o[1], o[2],  o[3]);
    dst[1] = make_uint4(o[4], o[5], o[6],  o[7]);
    dst[2] = make_uint4(o[8], o[9], o[10], o[11]);
}

// ---------------------------------------------------------------------------
// Kernel 2: sim = xn @ xn^T, fused exp-sum epilogue.
// sm_103a: TS-mode tcgen05 (A in TMEM cols 0..383, D double-buffered at
// 384/448), 8-deep cp.async B pipeline. Warps 0-3 epilogue (+A STTM
// prologue), warp 4 lane 0 MMA issuer, warps 5-6 B producers.
// ---------------------------------------------------------------------------
__global__ __launch_bounds__(256, 1) __cluster_dims__(1, 1, 1) void kgemm() {
    extern __shared__ char smem[];
    const int tid   = threadIdx.x;
    const int i0    = blockIdx.x * 128;
    const int jbase = blockIdx.y * COLS_PER_CTA;

#if defined(HAS_TCGEN05)
    const uint32_t sb  = smem_u32(smem);
    const int wid = tid >> 5;

    const uint32_t MB_BFULL = sb + 16;     // 8 barriers
    const uint32_t MB_BFREE = sb + 80;     // 8 barriers
    const uint32_t MB_MDONE = sb + 144;    // 2
    const uint32_t MB_DFREE = sb + 160;    // 2

    if (tid == 0) {
        #pragma unroll
        for (int s = 0; s < NSTAGE; s++) {
            MBARRIER_INIT(MB_BFULL + s * 8, 64);
            MBARRIER_INIT(MB_BFREE + s * 8, 1);
        }
        MBARRIER_INIT(MB_MDONE + 0, 1);   MBARRIER_INIT(MB_MDONE + 8, 1);
        MBARRIER_INIT(MB_DFREE + 0, 128); MBARRIER_INIT(MB_DFREE + 8, 128);
    }
    if (wid == 4) TCGEN05_ALLOC(sb, 512);
    __syncthreads();
    uint32_t tmem;
    asm volatile("ld.shared.b32 %0, [%1];" : "=r"(tmem) : "r"(sb));

    // ---- prologue: A row -> TMEM (thread tid handles row i0+tid) ----------
    if (tid < 128) {
        const uint4* arow = (const uint4*)(g_xn + (size_t)(i0 + tid) * DIM);
        const uint32_t woff = ((uint32_t)tid >> 5) << 21;
        #pragma unroll 1
        for (int u = 0; u < 6; u++) {
            uint32_t rr[64];
            #pragma unroll
            for (int v = 0; v < 16; v++)
                *(uint4*)&rr[v * 4] = arow[u * 16 + v];
            TCGEN05_ST_32X32B_X64(tmem + u * 64 + woff, rr);
        }
        TCGEN05_WAIT_ST();
        TCGEN05_FENCE_BEFORE();
    }
    __syncthreads();
    TCGEN05_FENCE_AFTER();   // pair the before-fence across the sync (all warps)

    if (wid < 4) {
        // ================= consumers: epilogue on D buffers =================
        const int l = tid & 31;
        const int i = i0 + wid * 32 + l;
        float partial = 0.f;
        #pragma unroll 1
        for (int t = 0; t < NTILE; t++) {
            const int b = t & 1;
            MBARRIER_WAIT_PARITY(MB_MDONE + b * 8, (t >> 1) & 1);
            TCGEN05_FENCE_AFTER();
            const int j0 = jbase + t * 64;
            #pragma unroll 1
            for (int g = 0; g < 2; g++) {
                uint32_t rr[32];
                TCGEN05_LD_32X32B_X32(rr, tmem + TMEM_D + b * 64 + g * 32);
                TCGEN05_WAIT_LD();
                const int jg = j0 + g * 32;
                unsigned di = (unsigned)(i - jg);
                unsigned dt = (unsigned)((i ^ 1) - jg);
                if (di < 32u || dt < 32u) {
                    #pragma unroll
                    for (int c = 0; c < 32; c++) {
                        float v = __uint_as_float(rr[c]);
                        int j = jg + c;
                        if (j == (i ^ 1)) g_target[i] = v;
                        if (j != i)
                            partial += fast_exp2(fmaf(v, EXPC, -EXPC));
                    }
                } else {
                    #pragma unroll
                    for (int c = 0; c < 32; c++)
                        partial += fast_exp2(fmaf(__uint_as_float(rr[c]), EXPC, -EXPC));
                }
            }
            TCGEN05_FENCE_BEFORE();
            MBARRIER_ARRIVE(MB_DFREE + b * 8);
        }
        g_partial[blockIdx.y][i] = partial;
    } else if (tid == 128) {
        // ================= MMA issuer =================
        #pragma unroll 1
        for (int t = 0; t < NTILE; t++) {
            const int b = t & 1;
            const uint32_t dD = tmem + TMEM_D + b * 64;
            if (t >= 2) {
                MBARRIER_WAIT_PARITY(MB_DFREE + b * 8, ((t >> 1) + 1) & 1);
                TCGEN05_FENCE_AFTER();
            }
            #pragma unroll 1
            for (int c = 0; c < KCPT; c++) {
                const int n = t * KCPT + c, s = n & (NSTAGE - 1), k = n >> 3;
                MBARRIER_WAIT_PARITY(MB_BFULL + s * 8, k & 1);
                #pragma unroll
                for (int sub = 0; sub < 2; sub++) {
                    uint64_t bd = make_desc(sb + B_OFF + s * STAGE_BYTES + sub * 8192);
                    uint32_t aT = tmem + (c * 8 + sub * 4) * 8;
                    #pragma unroll
                    for (int k4 = 0; k4 < 4; k4++)
                        mma_f16_ts(dD, aT + k4 * 8, bd + k4 * 2, IDESC,
                                   (uint32_t)((c | sub | k4) != 0));
                }
                TCGEN05_COMMIT(MB_BFREE + s * 8);
            }
            TCGEN05_COMMIT(MB_MDONE + b * 8);
        }
    } else if (wid == 5 || wid == 6) {
        // ================= B producers (64 threads) =================
        const int row = tid - 160;            // 0..63 (one j-row per thread)
        #pragma unroll 1
        for (int n = 0; n < NCHUNK; n++) {
            const int s = n & (NSTAGE - 1), k = n >> 3;
            if (k >= 1) MBARRIER_WAIT_PARITY(MB_BFREE + s * 8, (k - 1) & 1);
            const int t = n / KCPT, c = n % KCPT;
            const int j = jbase + t * 64 + row;
            const uint32_t stg = sb + B_OFF + s * STAGE_BYTES;
            const __nv_bfloat16* src = &g_xn[(size_t)j * DIM + c * 128];
            #pragma unroll
            for (int sub = 0; sub < 2; sub++)
                #pragma unroll
                for (int u = 0; u < 8; u++)
                    cp16(stg + sub * 8192 + SWZ((uint32_t)(row * 128 + u * 16)),
                         src + sub * 64 + u * 8);
            CP_COMMIT();
            if (n >= 2) {           // deferred arrive, distance 2
                CP_WAIT2();
                FENCE_ASYNC_SHARED();
                MBARRIER_ARRIVE(MB_BFULL + ((n - 2) & (NSTAGE - 1)) * 8);
            }
        }
        CP_WAIT1();
        FENCE_ASYNC_SHARED();
        MBARRIER_ARRIVE(MB_BFULL + ((NCHUNK - 2) & (NSTAGE - 1)) * 8);
        CP_WAIT0();
        FENCE_ASYNC_SHARED();
        MBARRIER_ARRIVE(MB_BFULL + ((NCHUNK - 1) & (NSTAGE - 1)) * 8);
    }
    // warp 7 and warp-4 lanes 1..31 fall through

    __syncthreads();
    if (wid == 4) {
        TCGEN05_RELINQ();
        TCGEN05_DEALLOC(tmem, 512);
    }
#else
    // =================== WMMA fallback (non-103a compile passes) ============
    using namespace nvcuda;
    __nv_bfloat16* SA = (__nv_bfloat16*)(smem);           // [64][40]
    __nv_bfloat16* SB = (__nv_bfloat16*)(smem + 8192);    // [64][40]
    float*         SC = (float*)(smem + 16384);           // [64][72]
    const int warp = tid >> 5;
    const int wm = warp >> 2, wn = warp & 3;
    const int r = tid >> 2, q = tid & 3;
    const int lr = tid >> 2, lc = (tid & 3) * 8;

    for (int ms = 0; ms < 2; ms++) {
        const int row0 = i0 + ms * 64;
        const int i = row0 + r;
        float partial = 0.f;
        for (int jt = 0; jt < COLS_PER_CTA / 64; jt++) {
            const int j0 = jbase + jt * 64;
            wmma::fragment<wmma::accumulator, 16, 16, 16, float> acc[2];
            #pragma unroll
            for (int m = 0; m < 2; m++) wmma::fill_fragment(acc[m], 0.0f);

            for (int kb = 0; kb < DIM; kb += 32) {
                __syncthreads();
                *(uint4*)&SA[lr * 40 + lc] = *(const uint4*)&g_xn[(size_t)(row0 + lr) * DIM + kb + lc];
                *(uint4*)&SB[lr * 40 + lc] = *(const uint4*)&g_xn[(size_t)(j0  + lr) * DIM + kb + lc];
                __syncthreads();
                #pragma unroll
                for (int kf = 0; kf < 2; kf++) {
                    wmma::fragment<wmma::matrix_b, 16, 16, 16, __nv_bfloat16, wmma::col_major> bf;
                    wmma::load_matrix_sync(bf, &SB[(wn * 16) * 40 + kf * 16], 40);
                    #pragma unroll
                    for (int m = 0; m < 2; m++) {
                        wmma::fragment<wmma::matrix_a, 16, 16, 16, __nv_bfloat16, wmma::row_major> af;
                        wmma::load_matrix_sync(af, &SA[(wm * 32 + m * 16) * 40 + kf * 16], 40);
                        wmma::mma_sync(acc[m], af, bf, acc[m]);
                    }
                }
            }
            #pragma unroll
            for (int m = 0; m < 2; m++)
                wmma::store_matrix_sync(&SC[(wm * 32 + m * 16) * 72 + wn * 16], acc[m], 72,
                                        wmma::mem_row_major);
            __syncthreads();

            const float* crow = &SC[r * 72 + q * 16];
            #pragma unroll
            for (int c = 0; c < 16; c++) {
                int j = j0 + q * 16 + c;
                float v = crow[c];
                if (j == (i ^ 1)) g_target[i] = v;
                if (j != i)
                    partial += fast_exp2(fmaf(v, EXPC, -EXPC));
            }
        }
        partial += __shfl_xor_sync(0xffffffffu, partial, 1);
        partial += __shfl_xor_sync(0xffffffffu, partial, 2);
        if (q == 0) g_partial[blockIdx.y][i] = partial;
        __syncthreads();
    }
#endif
}

// ---------------------------------------------------------------------------
// Kernel 3: loss_i = 20 + ln(S_i) - 20*sim_target_i ; out = mean(loss)
// ---------------------------------------------------------------------------
__global__ __launch_bounds__(1024) void kreduce(float* __restrict__ out) {
    int tid = threadIdx.x;
    float s = 0.f;
    for (int i = tid; i < NROWS; i += 1024) {
        float S = g_partial[0][i] + g_partial[1][i];
        s += 20.0f + LN2 * fast_lg2(S) - 20.0f * g_target[i];
    }
    #pragma unroll
    for (int o = 16; o; o >>= 1) s += __shfl_xor_sync(0xffffffffu, s, o);

    __shared__ float sw[32];
    if ((tid & 31) == 0) sw[tid >> 5] = s;
    __syncthreads();
    if (tid < 32) {
        s = sw[tid];
        #pragma unroll
        for (int o = 16; o; o >>= 1) s += __shfl_xor_sync(0xffffffffu, s, o);
        if (tid == 0) out[0] = s * (1.0f / NROWS);
    }
}

// ---------------------------------------------------------------------------
extern "C" void kernel_launch(void* const* d_in, const int* in_sizes, int n_in,
                              void* d_out, int out_size) {
    const float* x = (const float*)d_in[0];
    float* out = (float*)d_out;

    cudaFuncSetAttribute(kgemm, cudaFuncAttributeMaxDynamicSharedMemorySize, SMEM_TOTAL);

    knorm<<<NROWS / 8, 256>>>(x);
    kgemm<<<dim3(NROWS / 128, CHUNKS), 256, SMEM_TOTAL>>>();
    kreduce<<<1, 1024>>>(out);
}

// round 8
// speedup vs baseline: 5.1149x; 1.6038x over previous
#include <cuda_runtime.h>
#include <cuda.h>
#include <cuda_bf16.h>
#include <mma.h>
#include <cstdint>

#define NROWS 8192
#define DIM   768
#define CHUNKS 2                        // grid.y column halves
#define COLS_PER_CTA (NROWS / CHUNKS)   // 4096
#define NTILE (COLS_PER_CTA / 64)       // 64 column tiles of N=64
#define KCPT 6                          // K=128 chunks per tile (768/128)
#define NCHUNK (NTILE * KCPT)           // 384 pipeline chunks per CTA
#define NSTAGE 8                        // B pipeline depth
#define STAGE_BYTES 16384               // 64 rows x 2 x (64 rows' worth) sub-blocks

#define EXPC 28.853900817779268f
#define LN2  0.6931471805599453f

// smem: [0] tmem ptr | [16..80) BFULL[8] | [80..144) BFREE[8]
//       [144..160) MDONE[2] | [160..176) DFREE[2] | [1024) B stages
#define B_OFF 1024
#define SMEM_TOTAL (1024 + NSTAGE * STAGE_BYTES)   // 132096

// TMEM: A cols 0..383 (K=768 bf16, 8 cols per K=16), D at 384 + b*64
#define TMEM_D 384

// idesc kind::f16: F32 accum, BF16 a/b, N=64, M=128
#define IDESC ((1u<<4)|(1u<<7)|(1u<<10)|((64u/8u)<<17)|((128u/16u)<<24))

#define SWZ(o) ((o) ^ (((o) >> 3) & 0x70))

__device__ __align__(256) __nv_bfloat16 g_xn[(size_t)NROWS * DIM];
__device__ float g_partial[CHUNKS][NROWS];
__device__ float g_target[NROWS];

// ---------------------------------------------------------------------------
// PTX helpers
// ---------------------------------------------------------------------------
__device__ __forceinline__ uint32_t smem_u32(const void* p) {
    uint32_t a;
    asm("{ .reg .u64 t; cvta.to.shared.u64 t, %1; cvt.u32.u64 %0, t; }"
        : "=r"(a) : "l"(p));
    return a;
}
__device__ __forceinline__ float fast_exp2(float a) {
    float r; asm("ex2.approx.f32 %0, %1;" : "=f"(r) : "f"(a)); return r;
}
__device__ __forceinline__ float fast_lg2(float a) {
    float r; asm("lg2.approx.f32 %0, %1;" : "=f"(r) : "f"(a)); return r;
}
__device__ __forceinline__ uint32_t cluster_rank() {
    uint32_t r; asm("mov.u32 %0, %%cluster_ctarank;" : "=r"(r)); return r;
}
#define CLUSTER_SYNC() do { \
    asm volatile("barrier.cluster.arrive.aligned;" ::: "memory"); \
    asm volatile("barrier.cluster.wait.aligned;" ::: "memory"); } while (0)

#define MBARRIER_INIT(a, n) \
    asm volatile("mbarrier.init.shared.b64 [%0], %1;" :: "r"((uint32_t)(a)), "r"((uint32_t)(n)) : "memory")
#define MBARRIER_ARRIVE(a) \
    asm volatile("mbarrier.arrive.shared.b64 _, [%0];" :: "r"((uint32_t)(a)) : "memory")
#define MBARRIER_EXPECT_TX(a, tx) \
    asm volatile("mbarrier.arrive.expect_tx.shared.b64 _, [%0], %1;" \
        :: "r"((uint32_t)(a)), "r"((uint32_t)(tx)) : "memory")
#define MBARRIER_WAIT_PARITY(a, par) do { \
    uint32_t _m = (uint32_t)(a); uint32_t _p = (uint32_t)(par); uint32_t _d; \
    asm volatile("{\n\t.reg .pred p;\n\t" \
        "mbarrier.try_wait.parity.acquire.cta.shared::cta.b64 p, [%1], %2;\n\t" \
        "selp.b32 %0, 1, 0, p;\n\t}" : "=r"(_d) : "r"(_m), "r"(_p) : "memory"); \
    if (!_d) { \
        asm volatile("{\n\t.reg .pred P1;\n\t" \
            "WL_%=:\n\t" \
            "mbarrier.try_wait.parity.acquire.cta.shared::cta.b64 P1, [%0], %1, 0x989680;\n\t" \
            "@P1 bra.uni WD_%=;\n\t" \
            "bra.uni WL_%=;\n\t" \
            "WD_%=:\n\t}" :: "r"(_m), "r"(_p) : "memory"); \
    } } while (0)

#define TCGEN05_ALLOC(sa, n) \
    asm volatile("tcgen05.alloc.cta_group::1.sync.aligned.shared::cta.b32 [%0], %1;" \
        :: "r"((uint32_t)(sa)), "r"((uint32_t)(n)) : "memory")
#define TCGEN05_DEALLOC(t, n) \
    asm volatile("tcgen05.dealloc.cta_group::1.sync.aligned.b32 %0, %1;" :: "r"(t), "r"((uint32_t)(n)))
#define TCGEN05_RELINQ() \
    asm volatile("tcgen05.relinquish_alloc_permit.cta_group::1.sync.aligned;")
#define TCGEN05_COMMIT(a) \
    asm volatile("tcgen05.commit.cta_group::1.mbarrier::arrive::one.shared::cluster.b64 [%0];" \
        :: "r"((uint32_t)(a)) : "memory")
#define TCGEN05_COMMIT_MCAST(a, mask) \
    asm volatile("tcgen05.commit.cta_group::1.mbarrier::arrive::one.shared::cluster.multicast::cluster.b64 [%0], %1;" \
        :: "r"((uint32_t)(a)), "h"((uint16_t)(mask)) : "memory")
#define TCGEN05_FENCE_BEFORE() asm volatile("tcgen05.fence::before_thread_sync;" ::: "memory")
#define TCGEN05_FENCE_AFTER()  asm volatile("tcgen05.fence::after_thread_sync;" ::: "memory")
#define TCGEN05_WAIT_LD()      asm volatile("tcgen05.wait::ld.sync.aligned;" ::: "memory")
#define TCGEN05_WAIT_ST()      asm volatile("tcgen05.wait::st.sync.aligned;" ::: "memory")

// 2D TMA multicast load: delivers box + complete_tx to every CTA in mask.
#define TMA_2D_MCAST(dst, tmapp, cx, cy, mbar, mask) \
    asm volatile("cp.async.bulk.tensor.2d.shared::cluster.global.tile" \
        ".mbarrier::complete_tx::bytes.multicast::cluster [%0], [%1, {%2, %3}], [%4], %5;" \
        :: "r"((uint32_t)(dst)), "l"(tmapp), "r"((int)(cx)), "r"((int)(cy)), \
           "r"((uint32_t)(mbar)), "h"((uint16_t)(mask)) : "memory")

#define TCGEN05_LD_32X32B_X32(r, tmem_addr) \
    asm volatile( \
        "tcgen05.ld.sync.aligned.32x32b.x32.b32 " \
        "{%0, %1, %2, %3, %4, %5, %6, %7, " \
        " %8, %9, %10, %11, %12, %13, %14, %15, " \
        " %16, %17, %18, %19, %20, %21, %22, %23, " \
        " %24, %25, %26, %27, %28, %29, %30, %31}, [%32];" \
        : "=r"((r)[0]),  "=r"((r)[1]),  "=r"((r)[2]),  "=r"((r)[3]), \
          "=r"((r)[4]),  "=r"((r)[5]),  "=r"((r)[6]),  "=r"((r)[7]), \
          "=r"((r)[8]),  "=r"((r)[9]),  "=r"((r)[10]), "=r"((r)[11]), \
          "=r"((r)[12]), "=r"((r)[13]), "=r"((r)[14]), "=r"((r)[15]), \
          "=r"((r)[16]), "=r"((r)[17]), "=r"((r)[18]), "=r"((r)[19]), \
          "=r"((r)[20]), "=r"((r)[21]), "=r"((r)[22]), "=r"((r)[23]), \
          "=r"((r)[24]), "=r"((r)[25]), "=r"((r)[26]), "=r"((r)[27]), \
          "=r"((r)[28]), "=r"((r)[29]), "=r"((r)[30]), "=r"((r)[31]) \
        : "r"(tmem_addr))

#define TCGEN05_ST_32X32B_X64(tmem_addr, r) \
    asm volatile( \
        "tcgen05.st.sync.aligned.32x32b.x64.b32 [%0], " \
        "{%1, %2, %3, %4, %5, %6, %7, %8, " \
        " %9, %10, %11, %12, %13, %14, %15, %16, " \
        " %17, %18, %19, %20, %21, %22, %23, %24, " \
        " %25, %26, %27, %28, %29, %30, %31, %32, " \
        " %33, %34, %35, %36, %37, %38, %39, %40, " \
        " %41, %42, %43, %44, %45, %46, %47, %48, " \
        " %49, %50, %51, %52, %53, %54, %55, %56, " \
        " %57, %58, %59, %60, %61, %62, %63, %64};" \
        :: "r"(tmem_addr), \
           "r"((r)[0]),  "r"((r)[1]),  "r"((r)[2]),  "r"((r)[3]), \
           "r"((r)[4]),  "r"((r)[5]),  "r"((r)[6]),  "r"((r)[7]), \
           "r"((r)[8]),  "r"((r)[9]),  "r"((r)[10]), "r"((r)[11]), \
           "r"((r)[12]), "r"((r)[13]), "r"((r)[14]), "r"((r)[15]), \
           "r"((r)[16]), "r"((r)[17]), "r"((r)[18]), "r"((r)[19]), \
           "r"((r)[20]), "r"((r)[21]), "r"((r)[22]), "r"((r)[23]), \
           "r"((r)[24]), "r"((r)[25]), "r"((r)[26]), "r"((r)[27]), \
           "r"((r)[28]), "r"((r)[29]), "r"((r)[30]), "r"((r)[31]), \
           "r"((r)[32]), "r"((r)[33]), "r"((r)[34]), "r"((r)[35]), \
           "r"((r)[36]), "r"((r)[37]), "r"((r)[38]), "r"((r)[39]), \
           "r"((r)[40]), "r"((r)[41]), "r"((r)[42]), "r"((r)[43]), \
           "r"((r)[44]), "r"((r)[45]), "r"((r)[46]), "r"((r)[47]), \
           "r"((r)[48]), "r"((r)[49]), "r"((r)[50]), "r"((r)[51]), \
           "r"((r)[52]), "r"((r)[53]), "r"((r)[54]), "r"((r)[55]), \
           "r"((r)[56]), "r"((r)[57]), "r"((r)[58]), "r"((r)[59]), \
           "r"((r)[60]), "r"((r)[61]), "r"((r)[62]), "r"((r)[63]) \
        : "memory")

// SW128 SMEM descriptor (layout=2, version=1, LBO=1, SBO=64); +2 per K=16 bf16.
__device__ __forceinline__ uint64_t make_desc(uint32_t addr) {
    return ((uint64_t)2 << 61) | ((uint64_t)1 << 46) | ((uint64_t)64 << 32) |
           ((uint64_t)1 << 16) | (uint64_t)((addr >> 4) & 0x3FFF);
}

#if defined(__CUDA_ARCH__) && defined(__CUDA_ARCH_FEAT_SM103_ALL)
#define HAS_TCGEN05 1
// TS form: A in TMEM, B via SMEM descriptor
__device__ __forceinline__ void mma_f16_ts(uint32_t d, uint32_t a_tmem, uint64_t bd,
                                           uint32_t idesc, uint32_t en) {
    asm volatile(
        "{\n\t"
        ".reg .pred p;\n\t"
        "setp.ne.u32 p, %4, 0;\n\t"
        "tcgen05.mma.cta_group::1.kind::f16 [%0], [%1], %2, %3, {%5, %5, %5, %5}, p;\n\t"
        "}"
        :: "r"(d), "r"(a_tmem), "l"(bd), "r"(idesc), "r"(en), "r"(0u)
        : "memory");
}
#endif

// ---------------------------------------------------------------------------
// Kernel 1: warp-per-row normalize fp32 -> bf16
// ---------------------------------------------------------------------------
__global__ __launch_bounds__(256) void knorm(const float* __restrict__ x) {
    int row = (blockIdx.x << 3) + (threadIdx.x >> 5);
    int l   = threadIdx.x & 31;
    const float4* xr = (const float4*)(x + (size_t)row * DIM) + l * 6;

    float4 v[6];
    float ss = 0.f;
    #pragma unroll
    for (int u = 0; u < 6; u++) {
        v[u] = xr[u];
        ss = fmaf(v[u].x, v[u].x, ss);
        ss = fmaf(v[u].y, v[u].y, ss);
        ss = fmaf(v[u].z, v[u].z, ss);
        ss = fmaf(v[u].w, v[u].w, ss);
    }
    #pragma unroll
    for (int o = 16; o; o >>= 1) ss += __shfl_xor_sync(0xffffffffu, ss, o);
    float scale = 1.0f / fmaxf(sqrtf(ss), 1e-8f);

    uint32_t o[12];
    #pragma unroll
    for (int u = 0; u < 6; u++) {
        __nv_bfloat162 p0 = __floats2bfloat162_rn(v[u].x * scale, v[u].y * scale);
        __nv_bfloat162 p1 = __floats2bfloat162_rn(v[u].z * scale, v[u].w * scale);
        o[2 * u]     = *(uint32_t*)&p0;
        o[2 * u + 1] = *(uint32_t*)&p1;
    }
    uint4* dst = (uint4*)(g_xn + (size_t)row * DIM) + l * 3;
    dst[0] = make_uint4(o[0], o[1], o[2],  o[3]);
    dst[1] = make_uint4(o[4], o[5], o[6],  o[7]);
    dst[2] = make_uint4(o[8], o[9], o[10], o[11]);
}

// ---------------------------------------------------------------------------
// Kernel 2: sim = xn @ xn^T, fused exp-sum epilogue.
// Cluster of 2 CTAs (same jbase) cooperatively TMA-multicast B slices.
// Warps 0-3 epilogue (+A STTM prologue), warp 4 lane 0 MMA issuer,
// tid 192 TMA producer. BFREE gated by BOTH issuers via multicast commit.
// ---------------------------------------------------------------------------
__global__ __launch_bounds__(256, 1) __cluster_dims__(2, 1, 1)
void kgemm(const __grid_constant__ CUtensorMap tmap) {
    extern __shared__ char smem[];
    const int tid   = threadIdx.x;
    const int i0    = blockIdx.x * 128;
    const int jbase = blockIdx.y * COLS_PER_CTA;

#if defined(HAS_TCGEN05)
    const uint32_t sb  = smem_u32(smem);
    const int wid = tid >> 5;

    const uint32_t MB_BFULL = sb + 16;     // 8 barriers (count 1 + tx)
    const uint32_t MB_BFREE = sb + 80;     // 8 barriers (count 2: both issuers)
    const uint32_t MB_MDONE = sb + 144;    // 2
    const uint32_t MB_DFREE = sb + 160;    // 2

    if (tid == 0) {
        #pragma unroll
        for (int s = 0; s < NSTAGE; s++) {
            MBARRIER_INIT(MB_BFULL + s * 8, 1);
            MBARRIER_INIT(MB_BFREE + s * 8, 2);
        }
        MBARRIER_INIT(MB_MDONE + 0, 1);   MBARRIER_INIT(MB_MDONE + 8, 1);
        MBARRIER_INIT(MB_DFREE + 0, 128); MBARRIER_INIT(MB_DFREE + 8, 128);
    }
    if (wid == 4) TCGEN05_ALLOC(sb, 512);
    __syncthreads();
    uint32_t tmem;
    asm volatile("ld.shared.b32 %0, [%1];" : "=r"(tmem) : "r"(sb));

    // ---- prologue: A row -> TMEM (thread tid handles row i0+tid) ----------
    if (tid < 128) {
        const uint4* arow = (const uint4*)(g_xn + (size_t)(i0 + tid) * DIM);
        const uint32_t woff = ((uint32_t)tid >> 5) << 21;
        #pragma unroll 1
        for (int u = 0; u < 6; u++) {
            uint32_t rr[64];
            #pragma unroll
            for (int v = 0; v < 16; v++)
                *(uint4*)&rr[v * 4] = arow[u * 16 + v];
            TCGEN05_ST_32X32B_X64(tmem + u * 64 + woff, rr);
        }
        TCGEN05_WAIT_ST();
        TCGEN05_FENCE_BEFORE();
    }
    __syncthreads();
    TCGEN05_FENCE_AFTER();
    // Both CTAs' mbarriers + A must be ready before any multicast TMA/commit.
    CLUSTER_SYNC();

    if (wid < 4) {
        // ================= consumers: epilogue on D buffers =================
        const int l = tid & 31;
        const int i = i0 + wid * 32 + l;
        float partial = 0.f;
        #pragma unroll 1
        for (int t = 0; t < NTILE; t++) {
            const int b = t & 1;
            MBARRIER_WAIT_PARITY(MB_MDONE + b * 8, (t >> 1) & 1);
            TCGEN05_FENCE_AFTER();
            const int j0 = jbase + t * 64;
            uint32_t r0[32], r1[32];
            TCGEN05_LD_32X32B_X32(r0, tmem + TMEM_D + b * 64);
            TCGEN05_LD_32X32B_X32(r1, tmem + TMEM_D + b * 64 + 32);
            TCGEN05_WAIT_LD();
            #pragma unroll
            for (int g = 0; g < 2; g++) {
                const uint32_t* rr = g ? r1 : r0;
                const int jg = j0 + g * 32;
                unsigned di = (unsigned)(i - jg);
                unsigned dt = (unsigned)((i ^ 1) - jg);
                if (di < 32u || dt < 32u) {
                    #pragma unroll
                    for (int c = 0; c < 32; c++) {
                        float v = __uint_as_float(rr[c]);
                        int j = jg + c;
                        if (j == (i ^ 1)) g_target[i] = v;
                        if (j != i)
                            partial += fast_exp2(fmaf(v, EXPC, -EXPC));
                    }
                } else {
                    #pragma unroll
                    for (int c = 0; c < 32; c++)
                        partial += fast_exp2(fmaf(__uint_as_float(rr[c]), EXPC, -EXPC));
                }
            }
            TCGEN05_FENCE_BEFORE();
            MBARRIER_ARRIVE(MB_DFREE + b * 8);
        }
        g_partial[blockIdx.y][i] = partial;
    } else if (tid == 128) {
        // ================= MMA issuer =================
        #pragma unroll 1
        for (int t = 0; t < NTILE; t++) {
            const int b = t & 1;
            const uint32_t dD = tmem + TMEM_D + b * 64;
            if (t >= 2) {
                MBARRIER_WAIT_PARITY(MB_DFREE + b * 8, ((t >> 1) + 1) & 1);
                TCGEN05_FENCE_AFTER();
            }
            #pragma unroll 1
            for (int c = 0; c < KCPT; c++) {
                const int n = t * KCPT + c, s = n & (NSTAGE - 1), k = n >> 3;
                MBARRIER_WAIT_PARITY(MB_BFULL + s * 8, k & 1);
                #pragma unroll
                for (int sub = 0; sub < 2; sub++) {
                    uint64_t bd = make_desc(sb + B_OFF + s * STAGE_BYTES + sub * 8192);
                    uint32_t aT = tmem + (c * 8 + sub * 4) * 8;
                    #pragma unroll
                    for (int k4 = 0; k4 < 4; k4++)
                        mma_f16_ts(dD, aT + k4 * 8, bd + k4 * 2, IDESC,
                                   (uint32_t)((c | sub | k4) != 0));
                }
                // free stage s in BOTH CTAs only when each CTA's mmas are done
                TCGEN05_COMMIT_MCAST(MB_BFREE + s * 8, 0x3);
            }
            TCGEN05_COMMIT(MB_MDONE + b * 8);
        }
    } else if (tid == 192) {
        // ================= B producer: cooperative TMA multicast ============
        const int rank = (int)cluster_rank();        // 0/1 within pair
        #pragma unroll 1
        for (int n = 0; n < NCHUNK; n++) {
            const int s = n & (NSTAGE - 1), k = n >> 3;
            if (k >= 1) MBARRIER_WAIT_PARITY(MB_BFREE + s * 8, (k - 1) & 1);
            MBARRIER_EXPECT_TX(MB_BFULL + s * 8, STAGE_BYTES);
            const int t = n / KCPT, c = n % KCPT;
            const int y = jbase + t * 64 + rank * 32;      // this CTA's row slice
            const uint32_t stg = sb + B_OFF + s * STAGE_BYTES + rank * 4096;
            TMA_2D_MCAST(stg,        &tmap, c * 128,      y, MB_BFULL + s * 8, 0x3);
            TMA_2D_MCAST(stg + 8192, &tmap, c * 128 + 64, y, MB_BFULL + s * 8, 0x3);
        }
    }
    // warp 7, warp 5, rest of warps 4/6 fall through

    __syncthreads();
    if (wid == 4) {
        TCGEN05_RELINQ();
        TCGEN05_DEALLOC(tmem, 512);
    }
    CLUSTER_SYNC();   // no CTA exits while peer multicast may be in flight
#else
    // =================== WMMA fallback (non-103a compile passes) ============
    using namespace nvcuda;
    __nv_bfloat16* SA = (__nv_bfloat16*)(smem);           // [64][40]
    __nv_bfloat16* SB = (__nv_bfloat16*)(smem + 8192);    // [64][40]
    float*         SC = (float*)(smem + 16384);           // [64][72]
    const int warp = tid >> 5;
    const int wm = warp >> 2, wn = warp & 3;
    const int r = tid >> 2, q = tid & 3;
    const int lr = tid >> 2, lc = (tid & 3) * 8;

    for (int ms = 0; ms < 2; ms++) {
        const int row0 = i0 + ms * 64;
        const int i = row0 + r;
        float partial = 0.f;
        for (int jt = 0; jt < COLS_PER_CTA / 64; jt++) {
            const int j0 = jbase + jt * 64;
            wmma::fragment<wmma::accumulator, 16, 16, 16, float> acc[2];
            #pragma unroll
            for (int m = 0; m < 2; m++) wmma::fill_fragment(acc[m], 0.0f);

            for (int kb = 0; kb < DIM; kb += 32) {
                __syncthreads();
                *(uint4*)&SA[lr * 40 + lc] = *(const uint4*)&g_xn[(size_t)(row0 + lr) * DIM + kb + lc];
                *(uint4*)&SB[lr * 40 + lc] = *(const uint4*)&g_xn[(size_t)(j0  + lr) * DIM + kb + lc];
                __syncthreads();
                #pragma unroll
                for (int kf = 0; kf < 2; kf++) {
                    wmma::fragment<wmma::matrix_b, 16, 16, 16, __nv_bfloat16, wmma::col_major> bf;
                    wmma::load_matrix_sync(bf, &SB[(wn * 16) * 40 + kf * 16], 40);
                    #pragma unroll
                    for (int m = 0; m < 2; m++) {
                        wmma::fragment<wmma::matrix_a, 16, 16, 16, __nv_bfloat16, wmma::row_major> af;
                        wmma::load_matrix_sync(af, &SA[(wm * 32 + m * 16) * 40 + kf * 16], 40);
                        wmma::mma_sync(acc[m], af, bf, acc[m]);
                    }
                }
            }
            #pragma unroll
            for (int m = 0; m < 2; m++)
                wmma::store_matrix_sync(&SC[(wm * 32 + m * 16) * 72 + wn * 16], acc[m], 72,
                                        wmma::mem_row_major);
            __syncthreads();

            const float* crow = &SC[r * 72 + q * 16];
            #pragma unroll
            for (int c = 0; c < 16; c++) {
                int j = j0 + q * 16 + c;
                float v = crow[c];
                if (j == (i ^ 1)) g_target[i] = v;
                if (j != i)
                    partial += fast_exp2(fmaf(v, EXPC, -EXPC));
            }
        }
        partial += __shfl_xor_sync(0xffffffffu, partial, 1);
        partial += __shfl_xor_sync(0xffffffffu, partial, 2);
        if (q == 0) g_partial[blockIdx.y][i] = partial;
        __syncthreads();
    }
#endif
}

// ---------------------------------------------------------------------------
// Kernel 3: loss_i = 20 + ln(S_i) - 20*sim_target_i ; out = mean(loss)
// ---------------------------------------------------------------------------
__global__ __launch_bounds__(1024) void kreduce(float* __restrict__ out) {
    int tid = threadIdx.x;
    float s = 0.f;
    for (int i = tid; i < NROWS; i += 1024) {
        float S = g_partial[0][i] + g_partial[1][i];
        s += 20.0f + LN2 * fast_lg2(S) - 20.0f * g_target[i];
    }
    #pragma unroll
    for (int o = 16; o; o >>= 1) s += __shfl_xor_sync(0xffffffffu, s, o);

    __shared__ float sw[32];
    if ((tid & 31) == 0) sw[tid >> 5] = s;
    __syncthreads();
    if (tid < 32) {
        s = sw[tid];
        #pragma unroll
        for (int o = 16; o; o >>= 1) s += __shfl_xor_sync(0xffffffffu, s, o);
        if (tid == 0) out[0] = s * (1.0f / NROWS);
    }
}

// ---------------------------------------------------------------------------
typedef CUresult (*PFN_encodeTiled)(
    CUtensorMap*, CUtensorMapDataType, cuuint32_t, void*,
    const cuuint64_t*, const cuuint64_t*, const cuuint32_t*, const cuuint32_t*,
    CUtensorMapInterleave, CUtensorMapSwizzle, CUtensorMapL2promotion,
    CUtensorMapFloatOOBfill);

extern "C" void kernel_launch(void* const* d_in, const int* in_sizes, int n_in,
                              void* d_out, int out_size) {
    const float* x = (const float*)d_in[0];
    float* out = (float*)d_out;

    // Build tensormap for g_xn viewed as [NROWS, DIM] bf16, box [64, 32], SW128.
    // Host-CPU only (no enqueue) -> safe under graph capture; deterministic.
    static CUtensorMap tmap;
    void* fn = nullptr;
    cudaDriverEntryPointQueryResult qres;
    cudaGetDriverEntryPointByVersion("cuTensorMapEncodeTiled", &fn, 12000,
                                     cudaEnableDefault, &qres);
    void* xaddr = nullptr;
    cudaGetSymbolAddress(&xaddr, g_xn);
    if (fn && xaddr) {
        cuuint64_t dims[2]    = {(cuuint64_t)DIM, (cuuint64_t)NROWS};
        cuuint64_t strides[1] = {(cuuint64_t)DIM * 2};
        cuuint32_t box[2]     = {64, 32};
        cuuint32_t estr[2]    = {1, 1};
        ((PFN_encodeTiled)fn)(&tmap, CU_TENSOR_MAP_DATA_TYPE_BFLOAT16, 2, xaddr,
                              dims, strides, box, estr,
                              CU_TENSOR_MAP_INTERLEAVE_NONE,
                              CU_TENSOR_MAP_SWIZZLE_128B,
                              CU_TENSOR_MAP_L2_PROMOTION_L2_128B,
                              CU_TENSOR_MAP_FLOAT_OOB_FILL_NONE);
    }

    cudaFuncSetAttribute(kgemm, cudaFuncAttributeMaxDynamicSharedMemorySize, SMEM_TOTAL);

    knorm<<<NROWS / 8, 256>>>(x);
    kgemm<<<dim3(NROWS / 128, CHUNKS), 256, SMEM_TOTAL>>>(tmap);
    kreduce<<<1, 1024>>>(out);
}

// round 10
// speedup vs baseline: 11.0364x; 2.1577x over previous
#include <cuda_runtime.h>
#include <cuda.h>
#include <cuda_bf16.h>
#include <cuda_fp8.h>
#include <cstdint>

#define NROWS 8192
#define DIM   768
#define CHUNKS 2                        // grid.y column halves
#define COLS_PER_CTA (NROWS / CHUNKS)   // 4096
#define NTILE (COLS_PER_CTA / 128)      // 32 column tiles of N=128
#define KCPT  6                         // K=128 chunks per tile (768/128)
#define NCHUNK (NTILE * KCPT)           // 192 pipeline chunks per CTA
#define NSTAGE 8                        // B pipeline depth
#define STAGE_BYTES 16384               // 128 j-rows x 128 K fp8

#define EXPC  28.853900817779268f
#define EXPC2 (EXPC / 1024.0f)          // logits are 1024*sim (xn scaled by 32)
#define TSCALE (20.0f / 1024.0f)
#define LN2   0.6931471805599453f

// smem: [0] tmem ptr | [16..80) BFULL[8] | [80..144) BFREE[8]
//       [144..160) MDONE[2] | [160..176) DFREE[2] | [1024) B stages
#define B_OFF 1024
#define SMEM_TOTAL (1024 + NSTAGE * STAGE_BYTES)   // 132096

// TMEM: A cols 0..191 (K=768 e4m3, 4 B/col), D buffers at 192 + b*128
#define TMEM_D 192

// idesc kind::f8f6f4: F32 accum (bit4), a/b=E4M3 (0), N=128, M=128
#define IDESC8 ((1u<<4) | ((128u/8u)<<17) | ((128u/16u)<<24))

__device__ __align__(1024) uint8_t g_x8[(size_t)NROWS * DIM];  // xn*32, e4m3
__device__ float g_partial[CHUNKS][NROWS];
__device__ float g_target[NROWS];    // 1024*sim(i, i^1)

// ---------------------------------------------------------------------------
// PTX helpers
// ---------------------------------------------------------------------------
__device__ __forceinline__ uint32_t smem_u32(const void* p) {
    uint32_t a;
    asm("{ .reg .u64 t; cvta.to.shared.u64 t, %1; cvt.u32.u64 %0, t; }"
        : "=r"(a) : "l"(p));
    return a;
}
__device__ __forceinline__ float fast_exp2(float a) {
    float r; asm("ex2.approx.f32 %0, %1;" : "=f"(r) : "f"(a)); return r;
}
__device__ __forceinline__ float fast_lg2(float a) {
    float r; asm("lg2.approx.f32 %0, %1;" : "=f"(r) : "f"(a)); return r;
}
__device__ __forceinline__ uint32_t cluster_rank() {
    uint32_t r; asm("mov.u32 %0, %%cluster_ctarank;" : "=r"(r)); return r;
}
__device__ __forceinline__ uint16_t cvt_e4m3x2(float hi, float lo) {
    uint16_t p;
    asm("cvt.rn.satfinite.e4m3x2.f32 %0, %1, %2;" : "=h"(p) : "f"(hi), "f"(lo));
    return p;   // hi -> upper byte, lo -> lower byte
}
#define CLUSTER_SYNC() do { \
    asm volatile("barrier.cluster.arrive.aligned;" ::: "memory"); \
    asm volatile("barrier.cluster.wait.aligned;" ::: "memory"); } while (0)

#define MBARRIER_INIT(a, n) \
    asm volatile("mbarrier.init.shared.b64 [%0], %1;" :: "r"((uint32_t)(a)), "r"((uint32_t)(n)) : "memory")
#define MBARRIER_ARRIVE(a) \
    asm volatile("mbarrier.arrive.shared.b64 _, [%0];" :: "r"((uint32_t)(a)) : "memory")
#define MBARRIER_EXPECT_TX(a, tx) \
    asm volatile("mbarrier.arrive.expect_tx.shared.b64 _, [%0], %1;" \
        :: "r"((uint32_t)(a)), "r"((uint32_t)(tx)) : "memory")
#define MBARRIER_WAIT_PARITY(a, par) do { \
    uint32_t _m = (uint32_t)(a); uint32_t _p = (uint32_t)(par); uint32_t _d; \
    asm volatile("{\n\t.reg .pred p;\n\t" \
        "mbarrier.try_wait.parity.acquire.cta.shared::cta.b64 p, [%1], %2;\n\t" \
        "selp.b32 %0, 1, 0, p;\n\t}" : "=r"(_d) : "r"(_m), "r"(_p) : "memory"); \
    if (!_d) { \
        asm volatile("{\n\t.reg .pred P1;\n\t" \
            "WL_%=:\n\t" \
            "mbarrier.try_wait.parity.acquire.cta.shared::cta.b64 P1, [%0], %1, 0x989680;\n\t" \
            "@P1 bra.uni WD_%=;\n\t" \
            "bra.uni WL_%=;\n\t" \
            "WD_%=:\n\t}" :: "r"(_m), "r"(_p) : "memory"); \
    } } while (0)

#define TCGEN05_ALLOC(sa, n) \
    asm volatile("tcgen05.alloc.cta_group::1.sync.aligned.shared::cta.b32 [%0], %1;" \
        :: "r"((uint32_t)(sa)), "r"((uint32_t)(n)) : "memory")
#define TCGEN05_DEALLOC(t, n) \
    asm volatile("tcgen05.dealloc.cta_group::1.sync.aligned.b32 %0, %1;" :: "r"(t), "r"((uint32_t)(n)))
#define TCGEN05_RELINQ() \
    asm volatile("tcgen05.relinquish_alloc_permit.cta_group::1.sync.aligned;")
#define TCGEN05_COMMIT(a) \
    asm volatile("tcgen05.commit.cta_group::1.mbarrier::arrive::one.shared::cluster.b64 [%0];" \
        :: "r"((uint32_t)(a)) : "memory")
#define TCGEN05_COMMIT_MCAST(a, mask) \
    asm volatile("tcgen05.commit.cta_group::1.mbarrier::arrive::one.shared::cluster.multicast::cluster.b64 [%0], %1;" \
        :: "r"((uint32_t)(a)), "h"((uint16_t)(mask)) : "memory")
#define TCGEN05_FENCE_BEFORE() asm volatile("tcgen05.fence::before_thread_sync;" ::: "memory")
#define TCGEN05_FENCE_AFTER()  asm volatile("tcgen05.fence::after_thread_sync;" ::: "memory")
#define TCGEN05_WAIT_LD()      asm volatile("tcgen05.wait::ld.sync.aligned;" ::: "memory")
#define TCGEN05_WAIT_ST()      asm volatile("tcgen05.wait::st.sync.aligned;" ::: "memory")

// 2D TMA multicast load: delivers box + complete_tx to every CTA in mask.
#define TMA_2D_MCAST(dst, tmapp, cx, cy, mbar, mask) \
    asm volatile("cp.async.bulk.tensor.2d.shared::cluster.global.tile" \
        ".mbarrier::complete_tx::bytes.multicast::cluster [%0], [%1, {%2, %3}], [%4], %5;" \
        :: "r"((uint32_t)(dst)), "l"(tmapp), "r"((int)(cx)), "r"((int)(cy)), \
           "r"((uint32_t)(mbar)), "h"((uint16_t)(mask)) : "memory")

#define TCGEN05_LD_32X32B_X32(r, tmem_addr) \
    asm volatile( \
        "tcgen05.ld.sync.aligned.32x32b.x32.b32 " \
        "{%0, %1, %2, %3, %4, %5, %6, %7, " \
        " %8, %9, %10, %11, %12, %13, %14, %15, " \
        " %16, %17, %18, %19, %20, %21, %22, %23, " \
        " %24, %25, %26, %27, %28, %29, %30, %31}, [%32];" \
        : "=r"((r)[0]),  "=r"((r)[1]),  "=r"((r)[2]),  "=r"((r)[3]), \
          "=r"((r)[4]),  "=r"((r)[5]),  "=r"((r)[6]),  "=r"((r)[7]), \
          "=r"((r)[8]),  "=r"((r)[9]),  "=r"((r)[10]), "=r"((r)[11]), \
          "=r"((r)[12]), "=r"((r)[13]), "=r"((r)[14]), "=r"((r)[15]), \
          "=r"((r)[16]), "=r"((r)[17]), "=r"((r)[18]), "=r"((r)[19]), \
          "=r"((r)[20]), "=r"((r)[21]), "=r"((r)[22]), "=r"((r)[23]), \
          "=r"((r)[24]), "=r"((r)[25]), "=r"((r)[26]), "=r"((r)[27]), \
          "=r"((r)[28]), "=r"((r)[29]), "=r"((r)[30]), "=r"((r)[31]) \
        : "r"(tmem_addr))

#define TCGEN05_ST_32X32B_X64(tmem_addr, r) \
    asm volatile( \
        "tcgen05.st.sync.aligned.32x32b.x64.b32 [%0], " \
        "{%1, %2, %3, %4, %5, %6, %7, %8, " \
        " %9, %10, %11, %12, %13, %14, %15, %16, " \
        " %17, %18, %19, %20, %21, %22, %23, %24, " \
        " %25, %26, %27, %28, %29, %30, %31, %32, " \
        " %33, %34, %35, %36, %37, %38, %39, %40, " \
        " %41, %42, %43, %44, %45, %46, %47, %48, " \
        " %49, %50, %51, %52, %53, %54, %55, %56, " \
        " %57, %58, %59, %60, %61, %62, %63, %64};" \
        :: "r"(tmem_addr), \
           "r"((r)[0]),  "r"((r)[1]),  "r"((r)[2]),  "r"((r)[3]), \
           "r"((r)[4]),  "r"((r)[5]),  "r"((r)[6]),  "r"((r)[7]), \
           "r"((r)[8]),  "r"((r)[9]),  "r"((r)[10]), "r"((r)[11]), \
           "r"((r)[12]), "r"((r)[13]), "r"((r)[14]), "r"((r)[15]), \
           "r"((r)[16]), "r"((r)[17]), "r"((r)[18]), "r"((r)[19]), \
           "r"((r)[20]), "r"((r)[21]), "r"((r)[22]), "r"((r)[23]), \
           "r"((r)[24]), "r"((r)[25]), "r"((r)[26]), "r"((r)[27]), \
           "r"((r)[28]), "r"((r)[29]), "r"((r)[30]), "r"((r)[31]), \
           "r"((r)[32]), "r"((r)[33]), "r"((r)[34]), "r"((r)[35]), \
           "r"((r)[36]), "r"((r)[37]), "r"((r)[38]), "r"((r)[39]), \
           "r"((r)[40]), "r"((r)[41]), "r"((r)[42]), "r"((r)[43]), \
           "r"((r)[44]), "r"((r)[45]), "r"((r)[46]), "r"((r)[47]), \
           "r"((r)[48]), "r"((r)[49]), "r"((r)[50]), "r"((r)[51]), \
           "r"((r)[52]), "r"((r)[53]), "r"((r)[54]), "r"((r)[55]), \
           "r"((r)[56]), "r"((r)[57]), "r"((r)[58]), "r"((r)[59]), \
           "r"((r)[60]), "r"((r)[61]), "r"((r)[62]), "r"((r)[63]) \
        : "memory")

// SW128 SMEM descriptor (layout=2, version=1, LBO=1, SBO=64); +2 per K=32 fp8.
__device__ __forceinline__ uint64_t make_desc(uint32_t addr) {
    return ((uint64_t)2 << 61) | ((uint64_t)1 << 46) | ((uint64_t)64 << 32) |
           ((uint64_t)1 << 16) | (uint64_t)((addr >> 4) & 0x3FFF);
}

#if defined(__CUDA_ARCH__) && defined(__CUDA_ARCH_FEAT_SM103_ALL)
#define HAS_TCGEN05 1
// TS form, fp8: A in TMEM (e4m3 packed 4/col), B via SMEM descriptor.
__device__ __forceinline__ void mma_f8_ts(uint32_t d, uint32_t a_tmem, uint64_t bd,
                                          uint32_t idesc, uint32_t en) {
    asm volatile(
        "{\n\t"
        ".reg .pred p;\n\t"
        "setp.ne.u32 p, %4, 0;\n\t"
        "tcgen05.mma.cta_group::1.kind::f8f6f4 [%0], [%1], %2, %3, {%5, %5, %5, %5}, p;\n\t"
        "}"
        :: "r"(d), "r"(a_tmem), "l"(bd), "r"(idesc), "r"(en), "r"(0u)
        : "memory");
}
#endif

// ---------------------------------------------------------------------------
// Kernel 1: warp-per-row normalize fp32 -> e4m3 (scaled by 32)
// ---------------------------------------------------------------------------
__global__ __launch_bounds__(256) void knorm(const float* __restrict__ x) {
    int row = (blockIdx.x << 3) + (threadIdx.x >> 5);
    int l   = threadIdx.x & 31;
    const float4* xr = (const float4*)(x + (size_t)row * DIM) + l * 6;

    float4 v[6];
    float ss = 0.f;
    #pragma unroll
    for (int u = 0; u < 6; u++) {
        v[u] = xr[u];
        ss = fmaf(v[u].x, v[u].x, ss);
        ss = fmaf(v[u].y, v[u].y, ss);
        ss = fmaf(v[u].z, v[u].z, ss);
        ss = fmaf(v[u].w, v[u].w, ss);
    }
    #pragma unroll
    for (int o = 16; o; o >>= 1) ss += __shfl_xor_sync(0xffffffffu, ss, o);
    float scale = 32.0f / fmaxf(sqrtf(ss), 1e-8f);

    uint32_t o[6];
    #pragma unroll
    for (int u = 0; u < 6; u++) {
        uint32_t lo = cvt_e4m3x2(v[u].y * scale, v[u].x * scale);
        uint32_t hi = cvt_e4m3x2(v[u].w * scale, v[u].z * scale);
        o[u] = lo | (hi << 16);
    }
    uint32_t* dst = (uint32_t*)(g_x8 + (size_t)row * DIM) + l * 6;
    *(uint2*)&dst[0] = make_uint2(o[0], o[1]);
    *(uint2*)&dst[2] = make_uint2(o[2], o[3]);
    *(uint2*)&dst[4] = make_uint2(o[4], o[5]);
}

// ---------------------------------------------------------------------------
// Kernel 2: logits' = (32 xn)(32 xn)^T = 1024*sim, fused exp-sum epilogue.
// Cluster of 2 CTAs (same jbase) cooperatively TMA-multicast fp8 B chunks.
// Warps 0-3 epilogue (+A STTM prologue), warp 4 lane 0 fp8 MMA issuer,
// tid 192 TMA producer. N=128 D tiles double-buffered in TMEM.
// ---------------------------------------------------------------------------
__global__ __launch_bounds__(256, 1) __cluster_dims__(2, 1, 1)
void kgemm(const __grid_constant__ CUtensorMap tmap) {
    extern __shared__ char smem[];
    const int tid   = threadIdx.x;
    const int i0    = blockIdx.x * 128;
    const int jbase = blockIdx.y * COLS_PER_CTA;

#if defined(HAS_TCGEN05)
    const uint32_t sb  = smem_u32(smem);
    const int wid = tid >> 5;

    const uint32_t MB_BFULL = sb + 16;     // 8 barriers (count 1 + tx)
    const uint32_t MB_BFREE = sb + 80;     // 8 barriers (count 2: both issuers)
    const uint32_t MB_MDONE = sb + 144;    // 2
    const uint32_t MB_DFREE = sb + 160;    // 2

    if (tid == 0) {
        #pragma unroll
        for (int s = 0; s < NSTAGE; s++) {
            MBARRIER_INIT(MB_BFULL + s * 8, 1);
            MBARRIER_INIT(MB_BFREE + s * 8, 2);
        }
        MBARRIER_INIT(MB_MDONE + 0, 1);   MBARRIER_INIT(MB_MDONE + 8, 1);
        MBARRIER_INIT(MB_DFREE + 0, 128); MBARRIER_INIT(MB_DFREE + 8, 128);
    }
    if (wid == 4) TCGEN05_ALLOC(sb, 512);
    __syncthreads();
    uint32_t tmem;
    asm volatile("ld.shared.b32 %0, [%1];" : "=r"(tmem) : "r"(sb));

    // ---- prologue: A row (768 e4m3 = 192 u32) -> TMEM cols 0..191 ----------
    if (tid < 128) {
        const uint4* arow = (const uint4*)(g_x8 + (size_t)(i0 + tid) * DIM);
        const uint32_t woff = ((uint32_t)tid >> 5) << 21;
        #pragma unroll 1
        for (int u = 0; u < 3; u++) {
            uint32_t rr[64];
            #pragma unroll
            for (int v = 0; v < 16; v++)
                *(uint4*)&rr[v * 4] = arow[u * 16 + v];
            TCGEN05_ST_32X32B_X64(tmem + u * 64 + woff, rr);
        }
        TCGEN05_WAIT_ST();
        TCGEN05_FENCE_BEFORE();
    }
    __syncthreads();
    TCGEN05_FENCE_AFTER();
    // Both CTAs' mbarriers + A must be ready before any multicast TMA/commit.
    CLUSTER_SYNC();

    if (wid < 4) {
        // ================= consumers: epilogue on N=128 D buffers ===========
        const int l = tid & 31;
        const int i = i0 + wid * 32 + l;
        float partial = 0.f;
        #pragma unroll 1
        for (int t = 0; t < NTILE; t++) {
            const int b = t & 1;
            MBARRIER_WAIT_PARITY(MB_MDONE + b * 8, (t >> 1) & 1);
            TCGEN05_FENCE_AFTER();
            const int j0 = jbase + t * 128;
            #pragma unroll 1
            for (int h = 0; h < 2; h++) {
                uint32_t r0[32], r1[32];
                TCGEN05_LD_32X32B_X32(r0, tmem + TMEM_D + b * 128 + h * 64);
                TCGEN05_LD_32X32B_X32(r1, tmem + TMEM_D + b * 128 + h * 64 + 32);
                TCGEN05_WAIT_LD();
                #pragma unroll
                for (int g = 0; g < 2; g++) {
                    const uint32_t* rr = g ? r1 : r0;
                    const int jg = j0 + (h * 2 + g) * 32;
                    unsigned di = (unsigned)(i - jg);
                    unsigned dt = (unsigned)((i ^ 1) - jg);
                    if (di < 32u || dt < 32u) {
                        #pragma unroll
                        for (int c = 0; c < 32; c++) {
                            float v = __uint_as_float(rr[c]);
                            int j = jg + c;
                            if (j == (i ^ 1)) g_target[i] = v;
                            if (j != i)
                                partial += fast_exp2(fmaf(v, EXPC2, -EXPC));
                        }
                    } else {
                        #pragma unroll
                        for (int c = 0; c < 32; c++)
                            partial += fast_exp2(fmaf(__uint_as_float(rr[c]), EXPC2, -EXPC));
                    }
                }
            }
            TCGEN05_FENCE_BEFORE();
            MBARRIER_ARRIVE(MB_DFREE + b * 8);
        }
        g_partial[blockIdx.y][i] = partial;
    } else if (tid == 128) {
        // ================= MMA issuer (fp8 TS) =================
        #pragma unroll 1
        for (int t = 0; t < NTILE; t++) {
            const int b = t & 1;
            const uint32_t dD = tmem + TMEM_D + b * 128;
            if (t >= 2) {
                MBARRIER_WAIT_PARITY(MB_DFREE + b * 8, ((t >> 1) + 1) & 1);
                TCGEN05_FENCE_AFTER();
            }
            #pragma unroll 1
            for (int c = 0; c < KCPT; c++) {
                const int n = t * KCPT + c, s = n & (NSTAGE - 1), k = n >> 3;
                MBARRIER_WAIT_PARITY(MB_BFULL + s * 8, k & 1);
                uint64_t bd = make_desc(sb + B_OFF + s * STAGE_BYTES);
                #pragma unroll
                for (int k4 = 0; k4 < 4; k4++)       // K=32 per dispatch
                    mma_f8_ts(dD, tmem + (c * 4 + k4) * 8, bd + k4 * 2, IDESC8,
                              (uint32_t)((c | k4) != 0));
                // free stage s in BOTH CTAs only when each CTA's mmas are done
                TCGEN05_COMMIT_MCAST(MB_BFREE + s * 8, 0x3);
            }
            TCGEN05_COMMIT(MB_MDONE + b * 8);
        }
    } else if (tid == 192) {
        // ================= B producer: cooperative TMA multicast ============
        const int rank = (int)cluster_rank();        // 0/1 within pair
        #pragma unroll 1
        for (int n = 0; n < NCHUNK; n++) {
            const int s = n & (NSTAGE - 1), k = n >> 3;
            if (k >= 1) MBARRIER_WAIT_PARITY(MB_BFREE + s * 8, (k - 1) & 1);
            MBARRIER_EXPECT_TX(MB_BFULL + s * 8, STAGE_BYTES);
            const int t = n / KCPT, c = n % KCPT;
            const int y = jbase + t * 128 + rank * 64;     // this CTA's 64 rows
            const uint32_t stg = sb + B_OFF + s * STAGE_BYTES + rank * 8192;
            TMA_2D_MCAST(stg, &tmap, c * 128, y, MB_BFULL + s * 8, 0x3);
        }
    }
    // warp 7, warp 5, rest of warps 4/6 fall through

    __syncthreads();
    if (wid == 4) {
        TCGEN05_RELINQ();
        TCGEN05_DEALLOC(tmem, 512);
    }
    CLUSTER_SYNC();   // no CTA exits while peer multicast may be in flight
#else
    // ============ scalar fallback (non-103a compile passes; never runs) =====
    if (tid < 128) {
        const int i = i0 + tid;
        const uint8_t* xi = g_x8 + (size_t)i * DIM;
        float partial = 0.f;
        for (int j = jbase; j < jbase + COLS_PER_CTA; j++) {
            const uint8_t* xj = g_x8 + (size_t)j * DIM;
            float v = 0.f;
            for (int k = 0; k < DIM; k++) {
                float a = float(*reinterpret_cast<const __nv_fp8_e4m3*>(&xi[k]));
                float bq = float(*reinterpret_cast<const __nv_fp8_e4m3*>(&xj[k]));
                v = fmaf(a, bq, v);
            }
            if (j == (i ^ 1)) g_target[i] = v;
            if (j != i) partial += fast_exp2(fmaf(v, EXPC2, -EXPC));
        }
        g_partial[blockIdx.y][i] = partial;
    }
#endif
}

// ---------------------------------------------------------------------------
// Kernel 3: loss_i = 20 + ln(S_i) - (20/1024)*v_target_i ; out = mean(loss)
// ---------------------------------------------------------------------------
__global__ __launch_bounds__(1024) void kreduce(float* __restrict__ out) {
    int tid = threadIdx.x;
    float s = 0.f;
    for (int i = tid; i < NROWS; i += 1024) {
        float S = g_partial[0][i] + g_partial[1][i];
        s += 20.0f + LN2 * fast_lg2(S) - TSCALE * g_target[i];
    }
    #pragma unroll
    for (int o = 16; o; o >>= 1) s += __shfl_xor_sync(0xffffffffu, s, o);

    __shared__ float sw[32];
    if ((tid & 31) == 0) sw[tid >> 5] = s;
    __syncthreads();
    if (tid < 32) {
        s = sw[tid];
        #pragma unroll
        for (int o = 16; o; o >>= 1) s += __shfl_xor_sync(0xffffffffu, s, o);
        if (tid == 0) out[0] = s * (1.0f / NROWS);
    }
}

// ---------------------------------------------------------------------------
typedef CUresult (*PFN_encodeTiled)(
    CUtensorMap*, CUtensorMapDataType, cuuint32_t, void*,
    const cuuint64_t*, const cuuint64_t*, const cuuint32_t*, const cuuint32_t*,
    CUtensorMapInterleave, CUtensorMapSwizzle, CUtensorMapL2promotion,
    CUtensorMapFloatOOBfill);

extern "C" void kernel_launch(void* const* d_in, const int* in_sizes, int n_in,
                              void* d_out, int out_size) {
    const float* x = (const float*)d_in[0];
    float* out = (float*)d_out;

    // Tensormap for g_x8 as [NROWS, DIM] uint8, box [128, 64], SW128.
    // Host-CPU only (no enqueue) -> safe under graph capture; deterministic.
    static CUtensorMap tmap;
    void* fn = nullptr;
    cudaDriverEntryPointQueryResult qres;
    cudaGetDriverEntryPointByVersion("cuTensorMapEncodeTiled", &fn, 12000,
                                     cudaEnableDefault, &qres);
    void* xaddr = nullptr;
    cudaGetSymbolAddress(&xaddr, g_x8);
    if (fn && xaddr) {
        cuuint64_t dims[2]    = {(cuuint64_t)DIM, (cuuint64_t)NROWS};
        cuuint64_t strides[1] = {(cuuint64_t)DIM};
        cuuint32_t box[2]     = {128, 64};
        cuuint32_t estr[2]    = {1, 1};
        ((PFN_encodeTiled)fn)(&tmap, CU_TENSOR_MAP_DATA_TYPE_UINT8, 2, xaddr,
                              dims, strides, box, estr,
                              CU_TENSOR_MAP_INTERLEAVE_NONE,
                              CU_TENSOR_MAP_SWIZZLE_128B,
                              CU_TENSOR_MAP_L2_PROMOTION_L2_128B,
                              CU_TENSOR_MAP_FLOAT_OOB_FILL_NONE);
    }

    cudaFuncSetAttribute(kgemm, cudaFuncAttributeMaxDynamicSharedMemorySize, SMEM_TOTAL);

    knorm<<<NROWS / 8, 256>>>(x);
    kgemm<<<dim3(NROWS / 128, CHUNKS), 256, SMEM_TOTAL>>>(tmap);
    kreduce<<<1, 1024>>>(out);
}

// round 13
// speedup vs baseline: 11.1908x; 1.0140x over previous
#include <cuda_runtime.h>
#include <cuda.h>
#include <cuda_bf16.h>
#include <cuda_fp8.h>
#include <cstdint>

#define NROWS 8192
#define DIM   768
#define CHUNKS 2                        // grid.y column halves
#define COLS_PER_CTA (NROWS / CHUNKS)   // 4096
#define NTILE (COLS_PER_CTA / 128)      // 32 column tiles of N=128
#define KCPT  6                         // K=128 chunks per tile (768/128)
#define NCHUNK (NTILE * KCPT)           // 192 pipeline chunks per CTA
#define NSTAGE 8                        // B pipeline depth
#define STAGE_BYTES 16384               // 128 j-rows x 128 K fp8
#define NDBUF 4                         // D buffers in TMEM

#define EXPC  28.853900817779268f
#define EXPC2 (EXPC / 1024.0f)          // logits are 1024*sim (xn scaled by 32)
#define TSCALE (20.0f / 1024.0f)
#define LN2   0.6931471805599453f

// smem: [0] tmem ptr | [16..80) BFULL[8] | [80..144) BFREE[8]
//       [144..176) MDONE[4] | [176..208) DFREE[4] | [208..216) ABAR
//       [1024) A 6x16KB | [99328) B stages 8x16KB
#define A_OFF 1024
#define B_OFF (1024 + 6 * 16384)                      // 99328
#define SMEM_TOTAL (B_OFF + NSTAGE * STAGE_BYTES)     // 230400

// idesc kind::f8f6f4: F32 accum (bit4), a/b=E4M3 (0), N=128, M=128
#define IDESC8 ((1u<<4) | ((128u/8u)<<17) | ((128u/16u)<<24))

__device__ __align__(1024) uint8_t g_x8[(size_t)NROWS * DIM];  // xn*32, e4m3
__device__ float g_partial[CHUNKS][NROWS];
__device__ float g_target[NROWS];    // 1024*sim(i, i^1)

// ---------------------------------------------------------------------------
// PTX helpers
// ---------------------------------------------------------------------------
__device__ __forceinline__ uint32_t smem_u32(const void* p) {
    uint32_t a;
    asm("{ .reg .u64 t; cvta.to.shared.u64 t, %1; cvt.u32.u64 %0, t; }"
        : "=r"(a) : "l"(p));
    return a;
}
__device__ __forceinline__ float fast_exp2(float a) {
    float r; asm("ex2.approx.f32 %0, %1;" : "=f"(r) : "f"(a)); return r;
}
__device__ __forceinline__ float fast_lg2(float a) {
    float r; asm("lg2.approx.f32 %0, %1;" : "=f"(r) : "f"(a)); return r;
}
__device__ __forceinline__ uint32_t cluster_rank() {
    uint32_t r; asm("mov.u32 %0, %%cluster_ctarank;" : "=r"(r)); return r;
}
__device__ __forceinline__ uint16_t cvt_e4m3x2(float hi, float lo) {
    uint16_t p;
    asm("cvt.rn.satfinite.e4m3x2.f32 %0, %1, %2;" : "=h"(p) : "f"(hi), "f"(lo));
    return p;
}
#define CLUSTER_SYNC() do { \
    asm volatile("barrier.cluster.arrive.aligned;" ::: "memory"); \
    asm volatile("barrier.cluster.wait.aligned;" ::: "memory"); } while (0)

#define MBARRIER_INIT(a, n) \
    asm volatile("mbarrier.init.shared.b64 [%0], %1;" :: "r"((uint32_t)(a)), "r"((uint32_t)(n)) : "memory")
#define MBARRIER_ARRIVE(a) \
    asm volatile("mbarrier.arrive.shared.b64 _, [%0];" :: "r"((uint32_t)(a)) : "memory")
#define MBARRIER_EXPECT_TX(a, tx) \
    asm volatile("mbarrier.arrive.expect_tx.shared.b64 _, [%0], %1;" \
        :: "r"((uint32_t)(a)), "r"((uint32_t)(tx)) : "memory")
#define MBARRIER_WAIT_PARITY(a, par) do { \
    uint32_t _m = (uint32_t)(a); uint32_t _p = (uint32_t)(par); uint32_t _d; \
    asm volatile("{\n\t.reg .pred p;\n\t" \
        "mbarrier.try_wait.parity.acquire.cta.shared::cta.b64 p, [%1], %2;\n\t" \
        "selp.b32 %0, 1, 0, p;\n\t}" : "=r"(_d) : "r"(_m), "r"(_p) : "memory"); \
    if (!_d) { \
        asm volatile("{\n\t.reg .pred P1;\n\t" \
            "WL_%=:\n\t" \
            "mbarrier.try_wait.parity.acquire.cta.shared::cta.b64 P1, [%0], %1, 0x989680;\n\t" \
            "@P1 bra.uni WD_%=;\n\t" \
            "bra.uni WL_%=;\n\t" \
            "WD_%=:\n\t}" :: "r"(_m), "r"(_p) : "memory"); \
    } } while (0)

#define TCGEN05_ALLOC(sa, n) \
    asm volatile("tcgen05.alloc.cta_group::1.sync.aligned.shared::cta.b32 [%0], %1;" \
        :: "r"((uint32_t)(sa)), "r"((uint32_t)(n)) : "memory")
#define TCGEN05_DEALLOC(t, n) \
    asm volatile("tcgen05.dealloc.cta_group::1.sync.aligned.b32 %0, %1;" :: "r"(t), "r"((uint32_t)(n)))
#define TCGEN05_RELINQ() \
    asm volatile("tcgen05.relinquish_alloc_permit.cta_group::1.sync.aligned;")
#define TCGEN05_COMMIT(a) \
    asm volatile("tcgen05.commit.cta_group::1.mbarrier::arrive::one.shared::cluster.b64 [%0];" \
        :: "r"((uint32_t)(a)) : "memory")
#define TCGEN05_COMMIT_MCAST(a, mask) \
    asm volatile("tcgen05.commit.cta_group::1.mbarrier::arrive::one.shared::cluster.multicast::cluster.b64 [%0], %1;" \
        :: "r"((uint32_t)(a)), "h"((uint16_t)(mask)) : "memory")
#define TCGEN05_FENCE_BEFORE() asm volatile("tcgen05.fence::before_thread_sync;" ::: "memory")
#define TCGEN05_FENCE_AFTER()  asm volatile("tcgen05.fence::after_thread_sync;" ::: "memory")
#define TCGEN05_WAIT_LD()      asm volatile("tcgen05.wait::ld.sync.aligned;" ::: "memory")

// plain 2D TMA (shared::cta) and multicast variant
#define TMA_2D(dst, tmapp, cx, cy, mbar) \
    asm volatile("cp.async.bulk.tensor.2d.shared::cta.global.tile" \
        ".mbarrier::complete_tx::bytes [%0], [%1, {%2, %3}], [%4];" \
        :: "r"((uint32_t)(dst)), "l"(tmapp), "r"((int)(cx)), "r"((int)(cy)), \
           "r"((uint32_t)(mbar)) : "memory")
#define TMA_2D_MCAST(dst, tmapp, cx, cy, mbar, mask) \
    asm volatile("cp.async.bulk.tensor.2d.shared::cluster.global.tile" \
        ".mbarrier::complete_tx::bytes.multicast::cluster [%0], [%1, {%2, %3}], [%4], %5;" \
        :: "r"((uint32_t)(dst)), "l"(tmapp), "r"((int)(cx)), "r"((int)(cy)), \
           "r"((uint32_t)(mbar)), "h"((uint16_t)(mask)) : "memory")

#define TCGEN05_LD_32X32B_X32(r, tmem_addr) \
    asm volatile( \
        "tcgen05.ld.sync.aligned.32x32b.x32.b32 " \
        "{%0, %1, %2, %3, %4, %5, %6, %7, " \
        " %8, %9, %10, %11, %12, %13, %14, %15, " \
        " %16, %17, %18, %19, %20, %21, %22, %23, " \
        " %24, %25, %26, %27, %28, %29, %30, %31}, [%32];" \
        : "=r"((r)[0]),  "=r"((r)[1]),  "=r"((r)[2]),  "=r"((r)[3]), \
          "=r"((r)[4]),  "=r"((r)[5]),  "=r"((r)[6]),  "=r"((r)[7]), \
          "=r"((r)[8]),  "=r"((r)[9]),  "=r"((r)[10]), "=r"((r)[11]), \
          "=r"((r)[12]), "=r"((r)[13]), "=r"((r)[14]), "=r"((r)[15]), \
          "=r"((r)[16]), "=r"((r)[17]), "=r"((r)[18]), "=r"((r)[19]), \
          "=r"((r)[20]), "=r"((r)[21]), "=r"((r)[22]), "=r"((r)[23]), \
          "=r"((r)[24]), "=r"((r)[25]), "=r"((r)[26]), "=r"((r)[27]), \
          "=r"((r)[28]), "=r"((r)[29]), "=r"((r)[30]), "=r"((r)[31]) \
        : "r"(tmem_addr))

// SW128 SMEM descriptor (layout=2, version=1, LBO=1, SBO=64); +2 per K=32 fp8.
__device__ __forceinline__ uint64_t make_desc(uint32_t addr) {
    return ((uint64_t)2 << 61) | ((uint64_t)1 << 46) | ((uint64_t)64 << 32) |
           ((uint64_t)1 << 16) | (uint64_t)((addr >> 4) & 0x3FFF);
}

#if defined(__CUDA_ARCH__) && defined(__CUDA_ARCH_FEAT_SM103_ALL)
#define HAS_TCGEN05 1
// SS form, fp8: A and B both via SMEM descriptors (validated: test_mma_mxf8_512)
__device__ __forceinline__ void mma_f8_ss(uint32_t d, uint64_t ad, uint64_t bd,
                                          uint32_t idesc, uint32_t en) {
    asm volatile(
        "{\n\t"
        ".reg .pred p;\n\t"
        "setp.ne.u32 p, %4, 0;\n\t"
        "tcgen05.mma.cta_group::1.kind::f8f6f4 [%0], %1, %2, %3, {%5, %5, %5, %5}, p;\n\t"
        "}"
        :: "r"(d), "l"(ad), "l"(bd), "r"(idesc), "r"(en), "r"(0u)
        : "memory");
}
#endif

// ---------------------------------------------------------------------------
// Kernel 1: warp-per-row normalize fp32 -> e4m3 (scaled by 32)
// ---------------------------------------------------------------------------
__global__ __launch_bounds__(256) void knorm(const float* __restrict__ x) {
    int row = (blockIdx.x << 3) + (threadIdx.x >> 5);
    int l   = threadIdx.x & 31;
    const float4* xr = (const float4*)(x + (size_t)row * DIM) + l * 6;

    float4 v[6];
    float ss = 0.f;
    #pragma unroll
    for (int u = 0; u < 6; u++) {
        v[u] = xr[u];
        ss = fmaf(v[u].x, v[u].x, ss);
        ss = fmaf(v[u].y, v[u].y, ss);
        ss = fmaf(v[u].z, v[u].z, ss);
        ss = fmaf(v[u].w, v[u].w, ss);
    }
    #pragma unroll
    for (int o = 16; o; o >>= 1) ss += __shfl_xor_sync(0xffffffffu, ss, o);
    float scale = 32.0f / fmaxf(sqrtf(ss), 1e-8f);

    uint32_t o[6];
    #pragma unroll
    for (int u = 0; u < 6; u++) {
        uint32_t lo = cvt_e4m3x2(v[u].y * scale, v[u].x * scale);
        uint32_t hi = cvt_e4m3x2(v[u].w * scale, v[u].z * scale);
        o[u] = lo | (hi << 16);
    }
    uint32_t* dst = (uint32_t*)(g_x8 + (size_t)row * DIM) + l * 6;
    *(uint2*)&dst[0] = make_uint2(o[0], o[1]);
    *(uint2*)&dst[2] = make_uint2(o[2], o[3]);
    *(uint2*)&dst[4] = make_uint2(o[4], o[5]);
}

// ---------------------------------------------------------------------------
// Kernel 2: logits' = (32 xn)(32 xn)^T = 1024*sim, fused exp-sum epilogue.
// SS-mode fp8 tcgen05: A persistent in SMEM (6x16KB, loaded via 12 async TMA
// boxes), B 8-stage TMA-multicast pipeline (cluster of 2). D = 4 TMEM buffers
// of N=128 (issuer runs up to 4 tiles ahead of epilogue).
// Warps 0-3 epilogue, warp 4 lane 0 MMA issuer, tid 192 TMA producer.
// ---------------------------------------------------------------------------
__global__ __launch_bounds__(256, 1) __cluster_dims__(2, 1, 1)
void kgemm(const __grid_constant__ CUtensorMap tmap) {
    extern __shared__ char smem[];
    const int tid   = threadIdx.x;
    const int i0    = blockIdx.x * 128;
    const int jbase = blockIdx.y * COLS_PER_CTA;

#if defined(HAS_TCGEN05)
    const uint32_t sb  = smem_u32(smem);
    const int wid = tid >> 5;

    const uint32_t MB_BFULL = sb + 16;     // 8 (count 1 + tx)
    const uint32_t MB_BFREE = sb + 80;     // 8 (count 2: both issuers)
    const uint32_t MB_MDONE = sb + 144;    // 4 (count 1)
    const uint32_t MB_DFREE = sb + 176;    // 4 (count 128)
    const uint32_t MB_ABAR  = sb + 208;    // 1 (count 1 + tx 96KB)

    if (tid == 0) {
        #pragma unroll
        for (int s = 0; s < NSTAGE; s++) {
            MBARRIER_INIT(MB_BFULL + s * 8, 1);
            MBARRIER_INIT(MB_BFREE + s * 8, 2);
        }
        #pragma unroll
        for (int b = 0; b < NDBUF; b++) {
            MBARRIER_INIT(MB_MDONE + b * 8, 1);
            MBARRIER_INIT(MB_DFREE + b * 8, 128);
        }
        MBARRIER_INIT(MB_ABAR, 1);
    }
    if (wid == 4) TCGEN05_ALLOC(sb, 512);
    __syncthreads();
    uint32_t tmem;
    asm volatile("ld.shared.b32 %0, [%1];" : "=r"(tmem) : "r"(sb));
    // Both CTAs' mbarriers must be visible before any multicast TMA/commit.
    CLUSTER_SYNC();

    if (wid < 4) {
        // ================= consumers: epilogue on N=128 D buffers ===========
        const int l = tid & 31;
        const int i = i0 + wid * 32 + l;
        float partial = 0.f;
        #pragma unroll 1
        for (int t = 0; t < NTILE; t++) {
            const int b = t & (NDBUF - 1);
            MBARRIER_WAIT_PARITY(MB_MDONE + b * 8, (t >> 2) & 1);
            TCGEN05_FENCE_AFTER();
            const int j0 = jbase + t * 128;
            #pragma unroll 1
            for (int h = 0; h < 2; h++) {
                uint32_t r0[32], r1[32];
                TCGEN05_LD_32X32B_X32(r0, tmem + b * 128 + h * 64);
                TCGEN05_LD_32X32B_X32(r1, tmem + b * 128 + h * 64 + 32);
                TCGEN05_WAIT_LD();
                #pragma unroll
                for (int g = 0; g < 2; g++) {
                    const uint32_t* rr = g ? r1 : r0;
                    const int jg = j0 + (h * 2 + g) * 32;
                    unsigned di = (unsigned)(i - jg);
                    unsigned dt = (unsigned)((i ^ 1) - jg);
                    if (di < 32u || dt < 32u) {
                        #pragma unroll
                        for (int c = 0; c < 32; c++) {
                            float v = __uint_as_float(rr[c]);
                            int j = jg + c;
                            if (j == (i ^ 1)) g_target[i] = v;
                            if (j != i)
                                partial += fast_exp2(fmaf(v, EXPC2, -EXPC));
                        }
                    } else {
                        #pragma unroll
                        for (int c = 0; c < 32; c++)
                            partial += fast_exp2(fmaf(__uint_as_float(rr[c]), EXPC2, -EXPC));
                    }
                }
            }
            TCGEN05_FENCE_BEFORE();
            MBARRIER_ARRIVE(MB_DFREE + b * 8);
        }
        g_partial[blockIdx.y][i] = partial;
    } else if (tid == 128) {
        // ================= MMA issuer (fp8 SS) =================
        MBARRIER_WAIT_PARITY(MB_ABAR, 0);        // A resident in SMEM
        #pragma unroll 1
        for (int t = 0; t < NTILE; t++) {
            const int b = t & (NDBUF - 1);
            const uint32_t dD = tmem + b * 128;
            if (t >= NDBUF) {
                MBARRIER_WAIT_PARITY(MB_DFREE + b * 8, ((t >> 2) + 1) & 1);
                TCGEN05_FENCE_AFTER();
            }
            #pragma unroll 1
            for (int c = 0; c < KCPT; c++) {
                const int n = t * KCPT + c, s = n & (NSTAGE - 1), k = n >> 3;
                MBARRIER_WAIT_PARITY(MB_BFULL + s * 8, k & 1);
                uint64_t ad = make_desc(sb + A_OFF + c * 16384);
                uint64_t bd = make_desc(sb + B_OFF + s * STAGE_BYTES);
                #pragma unroll
                for (int k4 = 0; k4 < 4; k4++)       // K=32 per dispatch
                    mma_f8_ss(dD, ad + k4 * 2, bd + k4 * 2, IDESC8,
                              (uint32_t)((c | k4) != 0));
                // free stage s in BOTH CTAs only when each CTA's mmas are done
                TCGEN05_COMMIT_MCAST(MB_BFREE + s * 8, 0x3);
            }
            TCGEN05_COMMIT(MB_MDONE + b * 8);
        }
    } else if (tid == 192) {
        // ============ producer: A (async, plain TMA) then B (multicast) =====
        const int rank = (int)cluster_rank();        // 0/1 within pair
        MBARRIER_EXPECT_TX(MB_ABAR, 6 * 16384);
        #pragma unroll
        for (int c = 0; c < KCPT; c++) {
            TMA_2D(sb + A_OFF + c * 16384,        &tmap, c * 128, i0,      MB_ABAR);
            TMA_2D(sb + A_OFF + c * 16384 + 8192, &tmap, c * 128, i0 + 64, MB_ABAR);
        }
        #pragma unroll 1
        for (int n = 0; n < NCHUNK; n++) {
            const int s = n & (NSTAGE - 1), k = n >> 3;
            if (k >= 1) MBARRIER_WAIT_PARITY(MB_BFREE + s * 8, (k - 1) & 1);
            MBARRIER_EXPECT_TX(MB_BFULL + s * 8, STAGE_BYTES);
            const int t = n / KCPT, c = n % KCPT;
            const int y = jbase + t * 128 + rank * 64;     // this CTA's 64 rows
            const uint32_t stg = sb + B_OFF + s * STAGE_BYTES + rank * 8192;
            TMA_2D_MCAST(stg, &tmap, c * 128, y, MB_BFULL + s * 8, 0x3);
        }
    }
    // warp 7, warp 5, rest of warps 4/6 fall through

    __syncthreads();
    if (wid == 4) {
        TCGEN05_RELINQ();
        TCGEN05_DEALLOC(tmem, 512);
    }
    CLUSTER_SYNC();   // no CTA exits while peer multicast may be in flight
#else
    // ============ scalar fallback (non-103a compile passes; never runs) =====
    if (tid < 128) {
        const int i = i0 + tid;
        const uint8_t* xi = g_x8 + (size_t)i * DIM;
        float partial = 0.f;
        for (int j = jbase; j < jbase + COLS_PER_CTA; j++) {
            const uint8_t* xj = g_x8 + (size_t)j * DIM;
            float v = 0.f;
            for (int k = 0; k < DIM; k++) {
                float a = float(*reinterpret_cast<const __nv_fp8_e4m3*>(&xi[k]));
                float bq = float(*reinterpret_cast<const __nv_fp8_e4m3*>(&xj[k]));
                v = fmaf(a, bq, v);
            }
            if (j == (i ^ 1)) g_target[i] = v;
            if (j != i) partial += fast_exp2(fmaf(v, EXPC2, -EXPC));
        }
        g_partial[blockIdx.y][i] = partial;
    }
#endif
}

// ---------------------------------------------------------------------------
// Kernel 3: loss_i = 20 + ln(S_i) - (20/1024)*v_target_i ; out = mean(loss)
// ---------------------------------------------------------------------------
__global__ __launch_bounds__(1024) void kreduce(float* __restrict__ out) {
    int tid = threadIdx.x;
    float s = 0.f;
    for (int i = tid; i < NROWS; i += 1024) {
        float S = g_partial[0][i] + g_partial[1][i];
        s += 20.0f + LN2 * fast_lg2(S) - TSCALE * g_target[i];
    }
    #pragma unroll
    for (int o = 16; o; o >>= 1) s += __shfl_xor_sync(0xffffffffu, s, o);

    __shared__ float sw[32];
    if ((tid & 31) == 0) sw[tid >> 5] = s;
    __syncthreads();
    if (tid < 32) {
        s = sw[tid];
        #pragma unroll
        for (int o = 16; o; o >>= 1) s += __shfl_xor_sync(0xffffffffu, s, o);
        if (tid == 0) out[0] = s * (1.0f / NROWS);
    }
}

// ---------------------------------------------------------------------------
typedef CUresult (*PFN_encodeTiled)(
    CUtensorMap*, CUtensorMapDataType, cuuint32_t, void*,
    const cuuint64_t*, const cuuint64_t*, const cuuint32_t*, const cuuint32_t*,
    CUtensorMapInterleave, CUtensorMapSwizzle, CUtensorMapL2promotion,
    CUtensorMapFloatOOBfill);

extern "C" void kernel_launch(void* const* d_in, const int* in_sizes, int n_in,
                              void* d_out, int out_size) {
    const float* x = (const float*)d_in[0];
    float* out = (float*)d_out;

    // Tensormap for g_x8 as [NROWS, DIM] uint8, box [128, 64], SW128.
    // Host-CPU only (no enqueue) -> safe under graph capture; deterministic.
    static CUtensorMap tmap;
    void* fn = nullptr;
    cudaDriverEntryPointQueryResult qres;
    cudaGetDriverEntryPointByVersion("cuTensorMapEncodeTiled", &fn, 12000,
                                     cudaEnableDefault, &qres);
    void* xaddr = nullptr;
    cudaGetSymbolAddress(&xaddr, g_x8);
    if (fn && xaddr) {
        cuuint64_t dims[2]    = {(cuuint64_t)DIM, (cuuint64_t)NROWS};
        cuuint64_t strides[1] = {(cuuint64_t)DIM};
        cuuint32_t box[2]     = {128, 64};
        cuuint32_t estr[2]    = {1, 1};
        ((PFN_encodeTiled)fn)(&tmap, CU_TENSOR_MAP_DATA_TYPE_UINT8, 2, xaddr,
                              dims, strides, box, estr,
                              CU_TENSOR_MAP_INTERLEAVE_NONE,
                              CU_TENSOR_MAP_SWIZZLE_128B,
                              CU_TENSOR_MAP_L2_PROMOTION_L2_128B,
                              CU_TENSOR_MAP_FLOAT_OOB_FILL_NONE);
    }

    cudaFuncSetAttribute(kgemm, cudaFuncAttributeMaxDynamicSharedMemorySize, SMEM_TOTAL);

    knorm<<<NROWS / 8, 256>>>(x);
    kgemm<<<dim3(NROWS / 128, CHUNKS), 256, SMEM_TOTAL>>>(tmap);
    kreduce<<<1, 1024>>>(out);
}